// round 4
// baseline (speedup 1.0000x reference)
#include <cuda_runtime.h>
#include <cuda_bf16.h>
#include <math.h>

// ---------------------------------------------------------------------------
// Problem constants
// ---------------------------------------------------------------------------
#define BATCH 1024
#define P_PTS 128
#define TOK   (BATCH * P_PTS)     // 131072 tokens
#define NNET  8
#define HID   128
#define INF   66                   // IN_DIM = 6*10+6
#define INF_PAD 68                 // padded K for layer 1
#define LFREQ 10

// ---------------------------------------------------------------------------
// Device scratch (static: no allocations allowed)
// ---------------------------------------------------------------------------
__device__ float g_t[P_PTS];          // scalar_array
__device__ float g_diffs[P_PTS - 1]; // diff(scalar_array)
__device__ float g_X[INF * TOK];      // features, k-major: g_X[f*TOK + t]
__device__ float g_ev[NNET * TOK * 4]; // per-net MLP outputs

// ---------------------------------------------------------------------------
// Accurate sincos (double precision; immune to --use_fast_math rewrites).
// ---------------------------------------------------------------------------
__device__ __forceinline__ void sincos_acc(double x, double* sp, double* cp) {
    int k = __double2int_rn(x * 0.63661977236758138);   // round(x / (pi/2))
    double q = (double)k;
    double r = __fma_rn(q, -1.5707963267948966, x);
    r = __fma_rn(q, -6.123233995736766e-17, r);
    double r2 = r * r;
    double s = __fma_rn(r2, 2.7557319223985893e-06, -1.9841269841269841e-04);
    s = __fma_rn(r2, s, 8.3333333333333332e-03);
    s = __fma_rn(r2, s, -1.6666666666666666e-01);
    s = __fma_rn(r * r2, s, r);
    double c = __fma_rn(r2, -2.7557319223985888e-07, 2.4801587301587302e-05);
    c = __fma_rn(r2, c, -1.3888888888888889e-03);
    c = __fma_rn(r2, c, 4.1666666666666664e-02);
    c = __fma_rn(r2, c, -0.5);
    c = __fma_rn(r2, c, 1.0);
    switch (k & 3) {
        case 0: *sp = s;  *cp = c;  break;
        case 1: *sp = c;  *cp = -s; break;
        case 2: *sp = -s; *cp = -c; break;
        default:*sp = -c; *cp = s;  break;
    }
}

// ---------------------------------------------------------------------------
// Kernel 0: jax PARTITIONABLE threefry (default since jax 0.4.36):
//   per element i: counter lanes (x0 = hi = 0, x1 = lo = i)
//   For bit_width==32 the random bits are  y0 ^ y1  (lanes XORed).
// key = jax.random.key(42) -> (0, 42)
// ---------------------------------------------------------------------------
__global__ void k_init(const float* __restrict__ sstart,
                       const float* __restrict__ send) {
    __shared__ float st[P_PTS];
    int i = threadIdx.x;   // 0..127
    float start = *sstart, end = *send;
    {
        unsigned x0 = 0u;
        unsigned x1 = (unsigned)i;
        const unsigned ks0 = 0u;
        const unsigned ks1 = 42u;
        const unsigned ks2 = 0x1BD11BDAu ^ 0u ^ 42u;
        x0 += ks0; x1 += ks1;
#define TF_R(r) { x0 += x1; x1 = (x1 << (r)) | (x1 >> (32 - (r))); x1 ^= x0; }
        TF_R(13) TF_R(15) TF_R(26) TF_R(6)
        x0 += ks1; x1 += ks2 + 1u;
        TF_R(17) TF_R(29) TF_R(16) TF_R(24)
        x0 += ks2; x1 += ks0 + 2u;
        TF_R(13) TF_R(15) TF_R(26) TF_R(6)
        x0 += ks0; x1 += ks1 + 3u;
        TF_R(17) TF_R(29) TF_R(16) TF_R(24)
        x0 += ks1; x1 += ks2 + 4u;
        TF_R(13) TF_R(15) TF_R(26) TF_R(6)
        x0 += ks2; x1 += ks0 + 5u;
#undef TF_R
        unsigned bits = x0 ^ x1;   // partitionable 32-bit output: lanes XORed
        float u = __uint_as_float((bits >> 9) | 0x3f800000u) - 1.0f;
        float range = __fadd_rn(end, -start);
        float step  = __fdiv_rn(range, 127.0f);
        float basev = __fadd_rn(start, __fmul_rn((float)i, step));
        float tv    = __fadd_rn(basev, __fdiv_rn(__fmul_rn(u, range), 127.0f));
        st[i] = tv;
        g_t[i] = tv;
    }
    __syncthreads();
    if (i < 127) g_diffs[i] = __fadd_rn(st[i + 1], -st[i]);
}

// ---------------------------------------------------------------------------
// Kernel 1: positional encode (X transposed, k-major) + softmax splits.
// ang_l = rn(ray * float(2^l pi)) == 2^l * rn(ray * pi) EXACTLY, so compute
// one accurate base sincos per coord and double-angle up the frequency ladder.
// ---------------------------------------------------------------------------
__global__ void k_features(const float* __restrict__ ro,
                           const float* __restrict__ rd,
                           const float* __restrict__ Ws,
                           const float* __restrict__ bsv,
                           float* __restrict__ splits_out) {
    int t = blockIdx.x * blockDim.x + threadIdx.x;
    if (t >= TOK) return;
    int b = t >> 7;
    int p = t & 127;
    float tp = g_t[p];
    float o0 = ro[b * 3 + 0], o1 = ro[b * 3 + 1], o2 = ro[b * 3 + 2];
    float d0 = rd[b * 3 + 0], d1 = rd[b * 3 + 1], d2 = rd[b * 3 + 2];
    float r0 = __fadd_rn(__fmul_rn(d0, tp), o0);
    float r1 = __fadd_rn(__fmul_rn(d1, tp), o1);
    float r2 = __fadd_rn(__fmul_rn(d2, tp), o2);

    g_X[0 * TOK + t] = r0;
    g_X[1 * TOK + t] = r1;
    g_X[2 * TOK + t] = r2;

    const float pif = 3.14159274101257324f;  // float(np.pi)
    float rc[3] = {r0, r1, r2};
#pragma unroll
    for (int c = 0; c < 3; ++c) {
        double a = (double)__fmul_rn(rc[c], pif);
        double s, co;
        sincos_acc(a, &s, &co);
#pragma unroll
        for (int l = 0; l < LFREQ; ++l) {
            g_X[(3 + 6 * l + c) * TOK + t]     = (float)co;
            g_X[(3 + 6 * l + 3 + c) * TOK + t] = (float)s;
            double sc = s * co;
            double cc = co * co;
            s  = sc + sc;
            co = __fma_rn(2.0, cc, -1.0);
        }
    }
    g_X[63 * TOK + t] = d0;
    g_X[64 * TOK + t] = d1;
    g_X[65 * TOK + t] = d2;

    float lg[NNET];
#pragma unroll
    for (int n = 0; n < NNET; ++n)
        lg[n] = bsv[n] + r0 * Ws[0 * NNET + n] + r1 * Ws[1 * NNET + n] + r2 * Ws[2 * NNET + n];
    float mx = lg[0];
#pragma unroll
    for (int n = 1; n < NNET; ++n) mx = fmaxf(mx, lg[n]);
    float sum = 0.f;
    float e[NNET];
#pragma unroll
    for (int n = 0; n < NNET; ++n) { e[n] = expf(lg[n] - mx); sum += e[n]; }
    float inv = __fdiv_rn(1.0f, sum);
#pragma unroll
    for (int n = 0; n < NNET; ++n) splits_out[t * NNET + n] = e[n] * inv;
}

// ---------------------------------------------------------------------------
// Kernel 2: the 3-layer MLP for one (token-tile of 128, net) per block.
// ---------------------------------------------------------------------------
#define SM_X   0
#define SM_W1  8704
#define SM_W2  17408
#define SM_H1  33792
#define SM_H2  0
#define SM_B   50176
#define SMEM_FLOATS (50176 + 772)
#define SMEM_BYTES  (SMEM_FLOATS * 4)

template <int K>
__device__ __forceinline__ void gemm_tile(const float* __restrict__ A,   // [K][128] : A[k][h]
                                          const float* __restrict__ Bm,  // [K][128] : B[k][m]
                                          const float* __restrict__ bias,// [128] per h
                                          float* __restrict__ Cout,      // [128][128] : C[h][m]
                                          int tx8, int ty8) {
    float acc[8][8];
#pragma unroll
    for (int i = 0; i < 8; ++i) {
        float bv = bias[ty8 + i];
#pragma unroll
        for (int j = 0; j < 8; ++j) acc[i][j] = bv;
    }
#pragma unroll 4
    for (int k = 0; k < K; ++k) {
        float4 a0 = *reinterpret_cast<const float4*>(&A[k * 128 + ty8]);
        float4 a1 = *reinterpret_cast<const float4*>(&A[k * 128 + ty8 + 4]);
        float4 b0 = *reinterpret_cast<const float4*>(&Bm[k * 128 + tx8]);
        float4 b1 = *reinterpret_cast<const float4*>(&Bm[k * 128 + tx8 + 4]);
        float av[8] = {a0.x, a0.y, a0.z, a0.w, a1.x, a1.y, a1.z, a1.w};
        float bv[8] = {b0.x, b0.y, b0.z, b0.w, b1.x, b1.y, b1.z, b1.w};
#pragma unroll
        for (int i = 0; i < 8; ++i)
#pragma unroll
            for (int j = 0; j < 8; ++j)
                acc[i][j] = fmaf(av[i], bv[j], acc[i][j]);
    }
#pragma unroll
    for (int i = 0; i < 8; ++i) {
        float4 v0 = make_float4(fmaxf(acc[i][0], 0.f), fmaxf(acc[i][1], 0.f),
                                fmaxf(acc[i][2], 0.f), fmaxf(acc[i][3], 0.f));
        float4 v1 = make_float4(fmaxf(acc[i][4], 0.f), fmaxf(acc[i][5], 0.f),
                                fmaxf(acc[i][6], 0.f), fmaxf(acc[i][7], 0.f));
        *reinterpret_cast<float4*>(&Cout[(ty8 + i) * 128 + tx8])     = v0;
        *reinterpret_cast<float4*>(&Cout[(ty8 + i) * 128 + tx8 + 4]) = v1;
    }
}

extern __shared__ float sm[];

__global__ __launch_bounds__(256, 1)
void k_mlp(const float* __restrict__ W1, const float* __restrict__ b1,
           const float* __restrict__ W2, const float* __restrict__ b2,
           const float* __restrict__ W3, const float* __restrict__ b3) {
    int tid  = threadIdx.x;
    int net  = blockIdx.y;
    int t0   = blockIdx.x * 128;

    const float* W1n = W1 + net * INF * HID;
    const float* b1n = b1 + net * HID;
    const float* W2n = W2 + net * HID * HID;
    const float* b2n = b2 + net * HID;
    const float* W3n = W3 + net * HID * 4;
    const float* b3n = b3 + net * 4;

    for (int idx = tid; idx < INF_PAD * 128; idx += 256) {
        int k = idx >> 7, m = idx & 127;
        sm[SM_X + idx]  = (k < INF) ? g_X[k * TOK + t0 + m] : 0.f;
        sm[SM_W1 + idx] = (k < INF) ? W1n[idx] : 0.f;
    }
    for (int idx = tid; idx < 128 * 128; idx += 256)
        sm[SM_W2 + idx] = W2n[idx];
    if (tid < 128) {
        sm[SM_B + tid]       = b1n[tid];
        sm[SM_B + 128 + tid] = b2n[tid];
    }
    for (int idx = tid; idx < 512; idx += 256)
        sm[SM_B + 256 + idx] = W3n[idx];
    if (tid < 4) sm[SM_B + 768 + tid] = b3n[tid];
    __syncthreads();

    int tx8 = (tid & 15) * 8;
    int ty8 = (tid >> 4) * 8;

    gemm_tile<INF_PAD>(&sm[SM_W1], &sm[SM_X], &sm[SM_B], &sm[SM_H1], tx8, ty8);
    __syncthreads();
    gemm_tile<128>(&sm[SM_W2], &sm[SM_H1], &sm[SM_B + 128], &sm[SM_H2], tx8, ty8);
    __syncthreads();

    {
        int m  = tid & 127;
        int oh = tid >> 7;
        const float* W3s = &sm[SM_B + 256];
        float e0 = sm[SM_B + 768 + 2 * oh];
        float e1 = sm[SM_B + 768 + 2 * oh + 1];
#pragma unroll 4
        for (int k = 0; k < 128; ++k) {
            float h = sm[SM_H2 + k * 128 + m];
            e0 = fmaf(h, W3s[k * 4 + 2 * oh],     e0);
            e1 = fmaf(h, W3s[k * 4 + 2 * oh + 1], e1);
        }
        long base = ((long)net * TOK + (t0 + m)) * 4;
        g_ev[base + 2 * oh]     = e0;
        g_ev[base + 2 * oh + 1] = e1;
    }
}

// ---------------------------------------------------------------------------
// Kernel 3: combine nets with splits, volume-render per ray
// ---------------------------------------------------------------------------
__global__ void k_render(float* __restrict__ out) {
    const float* splits = out + BATCH * 3;
    __shared__ float s_scan[P_PTS];
    __shared__ float s_red[P_PTS];
    int b = blockIdx.x;
    int p = threadIdx.x;
    int t = b * P_PTS + p;

    float sp[NNET];
#pragma unroll
    for (int n = 0; n < NNET; ++n) sp[n] = splits[t * NNET + n];

    float ne0 = 0.f, ne1 = 0.f, ne2 = 0.f, ne3 = 0.f;
#pragma unroll
    for (int n = 0; n < NNET; ++n) {
        long base = ((long)n * TOK + t) * 4;
        ne0 = fmaf(g_ev[base + 0], sp[n], ne0);
        ne1 = fmaf(g_ev[base + 1], sp[n], ne1);
        ne2 = fmaf(g_ev[base + 2], sp[n], ne2);
        ne3 = fmaf(g_ev[base + 3], sp[n], ne3);
    }

    float diff = (p < 127) ? g_diffs[p] : 0.f;
    float sd = ne3 * diff;

    s_scan[p] = sd;
    __syncthreads();
#pragma unroll
    for (int off = 1; off < P_PTS; off <<= 1) {
        float v = (p >= off) ? s_scan[p - off] : 0.f;
        __syncthreads();
        s_scan[p] += v;
        __syncthreads();
    }
    float T = expf(s_scan[p]);
    float w = (p < 127) ? T * (1.0f - expf(-sd)) : 0.f;

    float col[3] = {w * ne0, w * ne1, w * ne2};
#pragma unroll
    for (int c = 0; c < 3; ++c) {
        s_red[p] = col[c];
        __syncthreads();
        for (int off = 64; off >= 1; off >>= 1) {
            if (p < off) s_red[p] += s_red[p + off];
            __syncthreads();
        }
        if (p == 0) out[b * 3 + c] = s_red[0];
        __syncthreads();
    }
}

// ---------------------------------------------------------------------------
// Launch
// ---------------------------------------------------------------------------
extern "C" void kernel_launch(void* const* d_in, const int* in_sizes, int n_in,
                              void* d_out, int out_size) {
    const float* ray_o = (const float*)d_in[0];
    const float* ray_d = (const float*)d_in[1];
    const float* s_st  = (const float*)d_in[2];
    const float* s_en  = (const float*)d_in[3];
    // d_in[4] = num_integration_points (hardcoded 128)
    const float* W1 = (const float*)d_in[5];
    const float* b1 = (const float*)d_in[6];
    const float* W2 = (const float*)d_in[7];
    const float* b2 = (const float*)d_in[8];
    const float* W3 = (const float*)d_in[9];
    const float* b3 = (const float*)d_in[10];
    const float* Ws = (const float*)d_in[11];
    const float* bs = (const float*)d_in[12];
    float* out = (float*)d_out;

    cudaFuncSetAttribute(k_mlp, cudaFuncAttributeMaxDynamicSharedMemorySize, SMEM_BYTES);

    k_init<<<1, 128>>>(s_st, s_en);
    k_features<<<TOK / 256, 256>>>(ray_o, ray_d, Ws, bs, out + BATCH * 3);
    dim3 grid(TOK / 128, NNET);
    k_mlp<<<grid, 256, SMEM_BYTES>>>(W1, b1, W2, b2, W3, b3);
    k_render<<<BATCH, P_PTS>>>(out);
}

// round 6
// speedup vs baseline: 1.5982x; 1.5982x over previous
#include <cuda_runtime.h>
#include <cuda_bf16.h>
#include <math.h>

// ---------------------------------------------------------------------------
// Problem constants
// ---------------------------------------------------------------------------
#define BATCH 1024
#define P_PTS 128
#define TOK   (BATCH * P_PTS)     // 131072 tokens
#define NNET  8
#define HID   128
#define INF   66                   // IN_DIM = 6*10+6
#define KPAD1 80                   // layer-1 K padded to multiple of 16
#define LFREQ 10

// strides (in bf16 elements) chosen so ldmatrix row-chunk strides are odd -> conflict-free
#define XS  88     // X^T rows [128 tok][88]
#define WS  136    // W1/W2 rows [k][136]

// ---------------------------------------------------------------------------
// Device scratch (static: no allocations allowed)
// ---------------------------------------------------------------------------
__device__ float g_t[P_PTS];
__device__ float g_diffs[P_PTS - 1];
__device__ float g_X[INF * TOK];       // features, k-major: g_X[f*TOK + t]
__device__ float g_ev[NNET * TOK * 4]; // per-net MLP outputs

// ---------------------------------------------------------------------------
// Accurate sincos (double precision; immune to --use_fast_math rewrites).
// ---------------------------------------------------------------------------
__device__ __forceinline__ void sincos_acc(double x, double* sp, double* cp) {
    int k = __double2int_rn(x * 0.63661977236758138);   // round(x / (pi/2))
    double q = (double)k;
    double r = __fma_rn(q, -1.5707963267948966, x);
    r = __fma_rn(q, -6.123233995736766e-17, r);
    double r2 = r * r;
    double s = __fma_rn(r2, 2.7557319223985893e-06, -1.9841269841269841e-04);
    s = __fma_rn(r2, s, 8.3333333333333332e-03);
    s = __fma_rn(r2, s, -1.6666666666666666e-01);
    s = __fma_rn(r * r2, s, r);
    double c = __fma_rn(r2, -2.7557319223985888e-07, 2.4801587301587302e-05);
    c = __fma_rn(r2, c, -1.3888888888888889e-03);
    c = __fma_rn(r2, c, 4.1666666666666664e-02);
    c = __fma_rn(r2, c, -0.5);
    c = __fma_rn(r2, c, 1.0);
    switch (k & 3) {
        case 0: *sp = s;  *cp = c;  break;
        case 1: *sp = c;  *cp = -s; break;
        case 2: *sp = -s; *cp = -c; break;
        default:*sp = -c; *cp = s;  break;
    }
}

// ---------------------------------------------------------------------------
// Kernel 0: jax partitionable threefry, key (0,42); bits = y0 ^ y1
// ---------------------------------------------------------------------------
__global__ void k_init(const float* __restrict__ sstart,
                       const float* __restrict__ send) {
    __shared__ float st[P_PTS];
    int i = threadIdx.x;
    float start = *sstart, end = *send;
    {
        unsigned x0 = 0u;
        unsigned x1 = (unsigned)i;
        const unsigned ks0 = 0u;
        const unsigned ks1 = 42u;
        const unsigned ks2 = 0x1BD11BDAu ^ 0u ^ 42u;
        x0 += ks0; x1 += ks1;
#define TF_R(r) { x0 += x1; x1 = (x1 << (r)) | (x1 >> (32 - (r))); x1 ^= x0; }
        TF_R(13) TF_R(15) TF_R(26) TF_R(6)
        x0 += ks1; x1 += ks2 + 1u;
        TF_R(17) TF_R(29) TF_R(16) TF_R(24)
        x0 += ks2; x1 += ks0 + 2u;
        TF_R(13) TF_R(15) TF_R(26) TF_R(6)
        x0 += ks0; x1 += ks1 + 3u;
        TF_R(17) TF_R(29) TF_R(16) TF_R(24)
        x0 += ks1; x1 += ks2 + 4u;
        TF_R(13) TF_R(15) TF_R(26) TF_R(6)
        x0 += ks2; x1 += ks0 + 5u;
#undef TF_R
        unsigned bits = x0 ^ x1;
        float u = __uint_as_float((bits >> 9) | 0x3f800000u) - 1.0f;
        float range = __fadd_rn(end, -start);
        float step  = __fdiv_rn(range, 127.0f);
        float basev = __fadd_rn(start, __fmul_rn((float)i, step));
        float tv    = __fadd_rn(basev, __fdiv_rn(__fmul_rn(u, range), 127.0f));
        st[i] = tv;
        g_t[i] = tv;
    }
    __syncthreads();
    if (i < 127) g_diffs[i] = __fadd_rn(st[i + 1], -st[i]);
}

// ---------------------------------------------------------------------------
// Kernel 1: positional encode (X transposed, k-major) + softmax splits.
// ---------------------------------------------------------------------------
__global__ void k_features(const float* __restrict__ ro,
                           const float* __restrict__ rd,
                           const float* __restrict__ Ws,
                           const float* __restrict__ bsv,
                           float* __restrict__ splits_out) {
    int t = blockIdx.x * blockDim.x + threadIdx.x;
    if (t >= TOK) return;
    int b = t >> 7;
    int p = t & 127;
    float tp = g_t[p];
    float o0 = ro[b * 3 + 0], o1 = ro[b * 3 + 1], o2 = ro[b * 3 + 2];
    float d0 = rd[b * 3 + 0], d1 = rd[b * 3 + 1], d2 = rd[b * 3 + 2];
    float r0 = __fadd_rn(__fmul_rn(d0, tp), o0);
    float r1 = __fadd_rn(__fmul_rn(d1, tp), o1);
    float r2 = __fadd_rn(__fmul_rn(d2, tp), o2);

    g_X[0 * TOK + t] = r0;
    g_X[1 * TOK + t] = r1;
    g_X[2 * TOK + t] = r2;

    const float pif = 3.14159274101257324f;  // float(np.pi)
    float rc[3] = {r0, r1, r2};
#pragma unroll
    for (int c = 0; c < 3; ++c) {
        double a = (double)__fmul_rn(rc[c], pif);
        double s, co;
        sincos_acc(a, &s, &co);
#pragma unroll
        for (int l = 0; l < LFREQ; ++l) {
            g_X[(3 + 6 * l + c) * TOK + t]     = (float)co;
            g_X[(3 + 6 * l + 3 + c) * TOK + t] = (float)s;
            double sc = s * co;
            double cc = co * co;
            s  = sc + sc;
            co = __fma_rn(2.0, cc, -1.0);
        }
    }
    g_X[63 * TOK + t] = d0;
    g_X[64 * TOK + t] = d1;
    g_X[65 * TOK + t] = d2;

    float lg[NNET];
#pragma unroll
    for (int n = 0; n < NNET; ++n)
        lg[n] = bsv[n] + r0 * Ws[0 * NNET + n] + r1 * Ws[1 * NNET + n] + r2 * Ws[2 * NNET + n];
    float mx = lg[0];
#pragma unroll
    for (int n = 1; n < NNET; ++n) mx = fmaxf(mx, lg[n]);
    float sum = 0.f;
    float e[NNET];
#pragma unroll
    for (int n = 0; n < NNET; ++n) { e[n] = expf(lg[n] - mx); sum += e[n]; }
    float inv = __fdiv_rn(1.0f, sum);
#pragma unroll
    for (int n = 0; n < NNET; ++n) splits_out[t * NNET + n] = e[n] * inv;
}

// ---------------------------------------------------------------------------
// Tensor-core MLP: mma.sync m16n8k16 bf16, 2-term split (hi+lo), 3 MMAs/product.
// Per block: one (128-token tile, net). 8 warps, each owns 16 tokens and chains
// all three layers in registers (layer-L C frags == layer-L+1 A frags).
// ---------------------------------------------------------------------------
// smem offsets (bytes)
#define OFF_XHI  0
#define OFF_XLO  (OFF_XHI + 128 * XS * 2)            // 22528
#define OFF_W1HI (OFF_XLO + 128 * XS * 2)            // 45056
#define OFF_W1LO (OFF_W1HI + KPAD1 * WS * 2)         // 66816
#define OFF_W2HI (OFF_W1LO + KPAD1 * WS * 2)         // 88576
#define OFF_W2LO (OFF_W2HI + 128 * WS * 2)           // 123392
#define OFF_W3HI (OFF_W2LO + 128 * WS * 2)           // 158208
#define OFF_W3LO (OFF_W3HI + 128 * 8 * 2)            // 160256
#define OFF_B1   (OFF_W3LO + 128 * 8 * 2)            // 162304
#define OFF_B2   (OFF_B1 + 128 * 4)                  // 162816
#define OFF_B3   (OFF_B2 + 128 * 4)                  // 163328
#define SMEM_BYTES (OFF_B3 + 8 * 4)                  // 163360

__device__ __forceinline__ unsigned sptr(const void* p) {
    return (unsigned)__cvta_generic_to_shared(p);
}
__device__ __forceinline__ void ldsm4(unsigned a, unsigned& r0, unsigned& r1,
                                      unsigned& r2, unsigned& r3) {
    asm volatile("ldmatrix.sync.aligned.m8n8.x4.shared.b16 {%0,%1,%2,%3}, [%4];"
                 : "=r"(r0), "=r"(r1), "=r"(r2), "=r"(r3) : "r"(a));
}
__device__ __forceinline__ void ldsm4t(unsigned a, unsigned& r0, unsigned& r1,
                                       unsigned& r2, unsigned& r3) {
    asm volatile("ldmatrix.sync.aligned.m8n8.x4.trans.shared.b16 {%0,%1,%2,%3}, [%4];"
                 : "=r"(r0), "=r"(r1), "=r"(r2), "=r"(r3) : "r"(a));
}
__device__ __forceinline__ void ldsm2t(unsigned a, unsigned& r0, unsigned& r1) {
    asm volatile("ldmatrix.sync.aligned.m8n8.x2.trans.shared.b16 {%0,%1}, [%2];"
                 : "=r"(r0), "=r"(r1) : "r"(a));
}
__device__ __forceinline__ void mma_bf16(float* d, const unsigned* a, unsigned b0, unsigned b1) {
    asm volatile("mma.sync.aligned.m16n8k16.row.col.f32.bf16.bf16.f32 "
                 "{%0,%1,%2,%3}, {%4,%5,%6,%7}, {%8,%9}, {%0,%1,%2,%3};"
                 : "+f"(d[0]), "+f"(d[1]), "+f"(d[2]), "+f"(d[3])
                 : "r"(a[0]), "r"(a[1]), "r"(a[2]), "r"(a[3]), "r"(b0), "r"(b1));
}
// split-pack two fp32 into bf16x2 (hi) and residual bf16x2 (lo); v0 -> low half
__device__ __forceinline__ unsigned packsplit(float v0, float v1, unsigned& lo) {
    __nv_bfloat16 h0 = __float2bfloat16_rn(v0);
    __nv_bfloat16 h1 = __float2bfloat16_rn(v1);
    __nv_bfloat16 l0 = __float2bfloat16_rn(v0 - __bfloat162float(h0));
    __nv_bfloat16 l1 = __float2bfloat16_rn(v1 - __bfloat162float(h1));
    lo = (unsigned)__bfloat16_as_ushort(l0) | ((unsigned)__bfloat16_as_ushort(l1) << 16);
    return (unsigned)__bfloat16_as_ushort(h0) | ((unsigned)__bfloat16_as_ushort(h1) << 16);
}
__device__ __forceinline__ void split_store(__nv_bfloat16* hi, __nv_bfloat16* lo,
                                            int idx, float v) {
    __nv_bfloat16 h = __float2bfloat16_rn(v);
    hi[idx] = h;
    lo[idx] = __float2bfloat16_rn(v - __bfloat162float(h));
}

extern __shared__ char smemc[];

__global__ __launch_bounds__(256, 1)
void k_mlp(const float* __restrict__ W1, const float* __restrict__ b1,
           const float* __restrict__ W2, const float* __restrict__ b2,
           const float* __restrict__ W3, const float* __restrict__ b3) {
    const int tid  = threadIdx.x;
    const int lane = tid & 31;
    const int warp = tid >> 5;
    const int net  = blockIdx.y;
    const int t0   = blockIdx.x * 128;

    __nv_bfloat16* sXhi  = (__nv_bfloat16*)(smemc + OFF_XHI);
    __nv_bfloat16* sXlo  = (__nv_bfloat16*)(smemc + OFF_XLO);
    __nv_bfloat16* sW1hi = (__nv_bfloat16*)(smemc + OFF_W1HI);
    __nv_bfloat16* sW1lo = (__nv_bfloat16*)(smemc + OFF_W1LO);
    __nv_bfloat16* sW2hi = (__nv_bfloat16*)(smemc + OFF_W2HI);
    __nv_bfloat16* sW2lo = (__nv_bfloat16*)(smemc + OFF_W2LO);
    __nv_bfloat16* sW3hi = (__nv_bfloat16*)(smemc + OFF_W3HI);
    __nv_bfloat16* sW3lo = (__nv_bfloat16*)(smemc + OFF_W3LO);
    float* sb1 = (float*)(smemc + OFF_B1);
    float* sb2 = (float*)(smemc + OFF_B2);
    float* sb3 = (float*)(smemc + OFF_B3);

    const float* W1n = W1 + net * INF * HID;
    const float* b1n = b1 + net * HID;
    const float* W2n = W2 + net * HID * HID;
    const float* b2n = b2 + net * HID;
    const float* W3n = W3 + net * HID * 4;
    const float* b3n = b3 + net * 4;

    // ---- cooperative loads + fp32 -> split-bf16 conversion ----
    for (int idx = tid; idx < KPAD1 * 128; idx += 256) {     // X^T (transpose) tile
        int f = idx >> 7, m = idx & 127;
        float v = (f < INF) ? g_X[f * TOK + t0 + m] : 0.f;
        split_store(sXhi, sXlo, m * XS + f, v);
    }
    for (int idx = tid; idx < KPAD1 * 128; idx += 256) {     // W1 [k][h]
        int k = idx >> 7, h = idx & 127;
        float v = (k < INF) ? W1n[k * HID + h] : 0.f;
        split_store(sW1hi, sW1lo, k * WS + h, v);
    }
    for (int idx = tid; idx < 128 * 128; idx += 256) {       // W2 [h][h2]
        int k = idx >> 7, h = idx & 127;
        split_store(sW2hi, sW2lo, k * WS + h, W2n[idx]);
    }
    for (int idx = tid; idx < 128 * 8; idx += 256) {         // W3 [h][o], pad o to 8
        int k = idx >> 3, o = idx & 7;
        float v = (o < 4) ? W3n[k * 4 + o] : 0.f;
        split_store(sW3hi, sW3lo, k * 8 + o, v);
    }
    if (tid < 128) { sb1[tid] = b1n[tid]; sb2[tid] = b2n[tid]; }
    if (tid < 8)   sb3[tid] = (tid < 4) ? b3n[tid] : 0.f;
    __syncthreads();

    // ---- per-warp fragment geometry ----
    const int m0   = warp * 16;                 // this warp's 16 tokens
    const int lrow = lane & 15;
    const int lch  = lane >> 4;                 // 0/1: second 8-wide chunk
    const int cb   = (lane & 3) * 2;            // accumulator column offset in tile

    const unsigned sbase   = sptr(smemc);
    const unsigned aXhi    = sbase + OFF_XHI  + ((m0 + lrow) * XS + lch * 8) * 2;
    const unsigned aXlo    = sbase + OFF_XLO  + ((m0 + lrow) * XS + lch * 8) * 2;
    const unsigned aW1hi   = sbase + OFF_W1HI + (lrow * WS + lch * 8) * 2;
    const unsigned aW1lo   = sbase + OFF_W1LO + (lrow * WS + lch * 8) * 2;
    const unsigned aW2hi   = sbase + OFF_W2HI + (lrow * WS + lch * 8) * 2;
    const unsigned aW2lo   = sbase + OFF_W2LO + (lrow * WS + lch * 8) * 2;
    const unsigned aW3hi   = sbase + OFF_W3HI + (lrow * 8) * 2;
    const unsigned aW3lo   = sbase + OFF_W3LO + (lrow * 8) * 2;

    // ============================ layer 1 ============================
    float acc[16][4];
#pragma unroll
    for (int j = 0; j < 16; ++j) {
        float bv0 = sb1[j * 8 + cb], bv1 = sb1[j * 8 + cb + 1];
        acc[j][0] = bv0; acc[j][1] = bv1; acc[j][2] = bv0; acc[j][3] = bv1;
    }
#pragma unroll
    for (int ks = 0; ks < KPAD1 / 16; ++ks) {            // 5 k-steps
        unsigned ah[4], al[4];
        ldsm4(aXhi + ks * 32, ah[0], ah[1], ah[2], ah[3]);
        ldsm4(aXlo + ks * 32, al[0], al[1], al[2], al[3]);
#pragma unroll
        for (int jp = 0; jp < 8; ++jp) {
            unsigned bh0, bh1, bh2, bh3, bl0, bl1, bl2, bl3;
            ldsm4t(aW1hi + (ks * 16 * WS + jp * 16) * 2, bh0, bh1, bh2, bh3);
            ldsm4t(aW1lo + (ks * 16 * WS + jp * 16) * 2, bl0, bl1, bl2, bl3);
            mma_bf16(acc[2 * jp],     ah, bh0, bh1);
            mma_bf16(acc[2 * jp],     ah, bl0, bl1);
            mma_bf16(acc[2 * jp],     al, bh0, bh1);
            mma_bf16(acc[2 * jp + 1], ah, bh2, bh3);
            mma_bf16(acc[2 * jp + 1], ah, bl2, bl3);
            mma_bf16(acc[2 * jp + 1], al, bh2, bh3);
        }
    }
    // relu + repack C frags -> layer-2 A frags (registers only)
    unsigned a2h[8][4], a2l[8][4];
#pragma unroll
    for (int kk = 0; kk < 8; ++kk) {
#pragma unroll
        for (int half = 0; half < 2; ++half) {
            int j = 2 * kk + half;
            float v0 = fmaxf(acc[j][0], 0.f), v1 = fmaxf(acc[j][1], 0.f);
            float v2 = fmaxf(acc[j][2], 0.f), v3 = fmaxf(acc[j][3], 0.f);
            a2h[kk][2 * half]     = packsplit(v0, v1, a2l[kk][2 * half]);
            a2h[kk][2 * half + 1] = packsplit(v2, v3, a2l[kk][2 * half + 1]);
        }
    }

    // ============================ layer 2 ============================
    float acc2[16][4];
#pragma unroll
    for (int j = 0; j < 16; ++j) {
        float bv0 = sb2[j * 8 + cb], bv1 = sb2[j * 8 + cb + 1];
        acc2[j][0] = bv0; acc2[j][1] = bv1; acc2[j][2] = bv0; acc2[j][3] = bv1;
    }
#pragma unroll
    for (int kk = 0; kk < 8; ++kk) {
#pragma unroll
        for (int jp = 0; jp < 8; ++jp) {
            unsigned bh0, bh1, bh2, bh3, bl0, bl1, bl2, bl3;
            ldsm4t(aW2hi + (kk * 16 * WS + jp * 16) * 2, bh0, bh1, bh2, bh3);
            ldsm4t(aW2lo + (kk * 16 * WS + jp * 16) * 2, bl0, bl1, bl2, bl3);
            mma_bf16(acc2[2 * jp],     a2h[kk], bh0, bh1);
            mma_bf16(acc2[2 * jp],     a2h[kk], bl0, bl1);
            mma_bf16(acc2[2 * jp],     a2l[kk], bh0, bh1);
            mma_bf16(acc2[2 * jp + 1], a2h[kk], bh2, bh3);
            mma_bf16(acc2[2 * jp + 1], a2h[kk], bl2, bl3);
            mma_bf16(acc2[2 * jp + 1], a2l[kk], bh2, bh3);
        }
    }
    // relu + repack -> layer-3 A frags
    unsigned a3h[8][4], a3l[8][4];
#pragma unroll
    for (int kk = 0; kk < 8; ++kk) {
#pragma unroll
        for (int half = 0; half < 2; ++half) {
            int j = 2 * kk + half;
            float v0 = fmaxf(acc2[j][0], 0.f), v1 = fmaxf(acc2[j][1], 0.f);
            float v2 = fmaxf(acc2[j][2], 0.f), v3 = fmaxf(acc2[j][3], 0.f);
            a3h[kk][2 * half]     = packsplit(v0, v1, a3l[kk][2 * half]);
            a3h[kk][2 * half + 1] = packsplit(v2, v3, a3l[kk][2 * half + 1]);
        }
    }

    // ============================ layer 3 (N=4 padded to 8) ============================
    float acc3[4];
    acc3[0] = sb3[cb]; acc3[1] = sb3[cb + 1]; acc3[2] = acc3[0]; acc3[3] = acc3[1];
#pragma unroll
    for (int kk = 0; kk < 8; ++kk) {
        unsigned bh0, bh1, bl0, bl1;
        ldsm2t(aW3hi + (kk * 16 * 8) * 2, bh0, bh1);
        ldsm2t(aW3lo + (kk * 16 * 8) * 2, bl0, bl1);
        mma_bf16(acc3, a3h[kk], bh0, bh1);
        mma_bf16(acc3, a3h[kk], bl0, bl1);
        mma_bf16(acc3, a3l[kk], bh0, bh1);
    }

    // store ev: cols 0-3 valid (lane%4 < 2)
    if ((lane & 3) < 2) {
        int row = t0 + m0 + (lane >> 2);
        long base = ((long)net * TOK + row) * 4 + cb;
        *(float2*)&g_ev[base] = make_float2(acc3[0], acc3[1]);
        base = ((long)net * TOK + row + 8) * 4 + cb;
        *(float2*)&g_ev[base] = make_float2(acc3[2], acc3[3]);
    }
}

// ---------------------------------------------------------------------------
// Kernel 3: combine nets with splits, volume-render per ray
// ---------------------------------------------------------------------------
__global__ void k_render(float* __restrict__ out) {
    const float* splits = out + BATCH * 3;
    __shared__ float s_scan[P_PTS];
    __shared__ float s_red[P_PTS];
    int b = blockIdx.x;
    int p = threadIdx.x;
    int t = b * P_PTS + p;

    float sp[NNET];
#pragma unroll
    for (int n = 0; n < NNET; ++n) sp[n] = splits[t * NNET + n];

    float ne0 = 0.f, ne1 = 0.f, ne2 = 0.f, ne3 = 0.f;
#pragma unroll
    for (int n = 0; n < NNET; ++n) {
        long base = ((long)n * TOK + t) * 4;
        ne0 = fmaf(g_ev[base + 0], sp[n], ne0);
        ne1 = fmaf(g_ev[base + 1], sp[n], ne1);
        ne2 = fmaf(g_ev[base + 2], sp[n], ne2);
        ne3 = fmaf(g_ev[base + 3], sp[n], ne3);
    }

    float diff = (p < 127) ? g_diffs[p] : 0.f;
    float sd = ne3 * diff;

    s_scan[p] = sd;
    __syncthreads();
#pragma unroll
    for (int off = 1; off < P_PTS; off <<= 1) {
        float v = (p >= off) ? s_scan[p - off] : 0.f;
        __syncthreads();
        s_scan[p] += v;
        __syncthreads();
    }
    float T = expf(s_scan[p]);
    float w = (p < 127) ? T * (1.0f - expf(-sd)) : 0.f;

    float col[3] = {w * ne0, w * ne1, w * ne2};
#pragma unroll
    for (int c = 0; c < 3; ++c) {
        s_red[p] = col[c];
        __syncthreads();
        for (int off = 64; off >= 1; off >>= 1) {
            if (p < off) s_red[p] += s_red[p + off];
            __syncthreads();
        }
        if (p == 0) out[b * 3 + c] = s_red[0];
        __syncthreads();
    }
}

// ---------------------------------------------------------------------------
// Launch
// ---------------------------------------------------------------------------
extern "C" void kernel_launch(void* const* d_in, const int* in_sizes, int n_in,
                              void* d_out, int out_size) {
    const float* ray_o = (const float*)d_in[0];
    const float* ray_d = (const float*)d_in[1];
    const float* s_st  = (const float*)d_in[2];
    const float* s_en  = (const float*)d_in[3];
    // d_in[4] = num_integration_points (hardcoded 128)
    const float* W1 = (const float*)d_in[5];
    const float* b1 = (const float*)d_in[6];
    const float* W2 = (const float*)d_in[7];
    const float* b2 = (const float*)d_in[8];
    const float* W3 = (const float*)d_in[9];
    const float* b3 = (const float*)d_in[10];
    const float* Ws = (const float*)d_in[11];
    const float* bs = (const float*)d_in[12];
    float* out = (float*)d_out;

    cudaFuncSetAttribute(k_mlp, cudaFuncAttributeMaxDynamicSharedMemorySize, SMEM_BYTES);

    k_init<<<1, 128>>>(s_st, s_en);
    k_features<<<TOK / 256, 256>>>(ray_o, ray_d, Ws, bs, out + BATCH * 3);
    dim3 grid(TOK / 128, NNET);
    k_mlp<<<grid, 256, SMEM_BYTES>>>(W1, b1, W2, b2, W3, b3);
    k_render<<<BATCH, P_PTS>>>(out);
}

// round 8
// speedup vs baseline: 3.0349x; 1.8990x over previous
#include <cuda_runtime.h>
#include <cuda_bf16.h>
#include <math.h>

// ---------------------------------------------------------------------------
// Problem constants
// ---------------------------------------------------------------------------
#define BATCH 1024
#define P_PTS 128
#define TOK   (BATCH * P_PTS)     // 131072 tokens
#define NNET  8
#define HID   128
#define INF   66                   // IN_DIM = 6*10+6
#define KPAD1 80                   // layer-1 K padded to multiple of 16
#define LFREQ 10

// strides (bf16 elems): odd multiples of 8 -> conflict-free ldmatrix
#define XS  88     // X^T rows [128 tok][88]
#define WS  136    // W1/W2 rows [k][136]

#define W1T (KPAD1 * WS)   // 10880 elems
#define W2T (128 * WS)     // 17408
#define W3T (128 * 8)      // 1024
// blob byte offsets (within per-net weight blob)
#define B_W1HI 0
#define B_W1LO (B_W1HI + W1T * 2)   // 21760
#define B_W2HI (B_W1LO + W1T * 2)   // 43520
#define B_W2LO (B_W2HI + W2T * 2)   // 78336
#define B_W3HI (B_W2LO + W2T * 2)   // 113152
#define B_W3LO (B_W3HI + W3T * 2)   // 115200
#define BLOB_BYTES (B_W3LO + W3T * 2)  // 117248

// k_mlp smem layout (bytes)
#define OFF_W   0
#define OFF_B   BLOB_BYTES              // 117248 : b1[128] b2[128] b3[8] floats
#define OFF_X0  (OFF_B + 1056)          // 118304
#define XBUF_BYTES 45056                // hi 22528 + lo 22528
#define OFF_X1  (OFF_X0 + XBUF_BYTES)   // 163360
#define SMEM_BYTES (OFF_X1 + XBUF_BYTES) // 208416

#define GX 128                          // blocks per net
#define TILES_PER_BLOCK (1024 / GX)     // 8

// ---------------------------------------------------------------------------
// Device scratch
// ---------------------------------------------------------------------------
__device__ float g_t[P_PTS];
__device__ float g_diffs[P_PTS - 1];
__device__ __align__(16) __nv_bfloat16 g_Xhi[TOK * 80];  // [t][80] row-major
__device__ __align__(16) __nv_bfloat16 g_Xlo[TOK * 80];
__device__ __align__(16) __nv_bfloat16 g_wblob[NNET][BLOB_BYTES / 2];
__device__ __align__(16) float g_bias[NNET][264];        // b1,b2,b3pad
__device__ float g_ev[NNET * TOK * 4];

// ---------------------------------------------------------------------------
// Accurate sincos (double precision; immune to --use_fast_math rewrites).
// ---------------------------------------------------------------------------
__device__ __forceinline__ void sincos_acc(double x, double* sp, double* cp) {
    int k = __double2int_rn(x * 0.63661977236758138);
    double q = (double)k;
    double r = __fma_rn(q, -1.5707963267948966, x);
    r = __fma_rn(q, -6.123233995736766e-17, r);
    double r2 = r * r;
    double s = __fma_rn(r2, 2.7557319223985893e-06, -1.9841269841269841e-04);
    s = __fma_rn(r2, s, 8.3333333333333332e-03);
    s = __fma_rn(r2, s, -1.6666666666666666e-01);
    s = __fma_rn(r * r2, s, r);
    double c = __fma_rn(r2, -2.7557319223985888e-07, 2.4801587301587302e-05);
    c = __fma_rn(r2, c, -1.3888888888888889e-03);
    c = __fma_rn(r2, c, 4.1666666666666664e-02);
    c = __fma_rn(r2, c, -0.5);
    c = __fma_rn(r2, c, 1.0);
    switch (k & 3) {
        case 0: *sp = s;  *cp = c;  break;
        case 1: *sp = c;  *cp = -s; break;
        case 2: *sp = -s; *cp = -c; break;
        default:*sp = -c; *cp = s;  break;
    }
}

// ---------------------------------------------------------------------------
// Kernel 0: jax partitionable threefry, key (0,42); bits = y0 ^ y1
// ---------------------------------------------------------------------------
__global__ void k_init(const float* __restrict__ sstart,
                       const float* __restrict__ send) {
    __shared__ float st[P_PTS];
    int i = threadIdx.x;
    float start = *sstart, end = *send;
    {
        unsigned x0 = 0u;
        unsigned x1 = (unsigned)i;
        const unsigned ks0 = 0u;
        const unsigned ks1 = 42u;
        const unsigned ks2 = 0x1BD11BDAu ^ 0u ^ 42u;
        x0 += ks0; x1 += ks1;
#define TF_R(r) { x0 += x1; x1 = (x1 << (r)) | (x1 >> (32 - (r))); x1 ^= x0; }
        TF_R(13) TF_R(15) TF_R(26) TF_R(6)
        x0 += ks1; x1 += ks2 + 1u;
        TF_R(17) TF_R(29) TF_R(16) TF_R(24)
        x0 += ks2; x1 += ks0 + 2u;
        TF_R(13) TF_R(15) TF_R(26) TF_R(6)
        x0 += ks0; x1 += ks1 + 3u;
        TF_R(17) TF_R(29) TF_R(16) TF_R(24)
        x0 += ks1; x1 += ks2 + 4u;
        TF_R(13) TF_R(15) TF_R(26) TF_R(6)
        x0 += ks2; x1 += ks0 + 5u;
#undef TF_R
        unsigned bits = x0 ^ x1;
        float u = __uint_as_float((bits >> 9) | 0x3f800000u) - 1.0f;
        float range = __fadd_rn(end, -start);
        float step  = __fdiv_rn(range, 127.0f);
        float basev = __fadd_rn(start, __fmul_rn((float)i, step));
        float tv    = __fadd_rn(basev, __fdiv_rn(__fmul_rn(u, range), 127.0f));
        st[i] = tv;
        g_t[i] = tv;
    }
    __syncthreads();
    if (i < 127) g_diffs[i] = __fadd_rn(st[i + 1], -st[i]);
}

// ---------------------------------------------------------------------------
// Kernel P: pre-split weights into per-net bf16 blobs (smem-tile layout)
// ---------------------------------------------------------------------------
__global__ void k_prep(const float* __restrict__ W1, const float* __restrict__ b1,
                       const float* __restrict__ W2, const float* __restrict__ b2,
                       const float* __restrict__ W3, const float* __restrict__ b3) {
    int net = blockIdx.x;
    int tid = threadIdx.x;
    __nv_bfloat16* blob = g_wblob[net];
    const float* W1n = W1 + net * INF * HID;
    const float* W2n = W2 + net * HID * HID;
    const float* W3n = W3 + net * HID * 4;

    for (int idx = tid; idx < W1T; idx += 256) {
        int k = idx / WS, hs = idx % WS;
        float v = (hs < HID && k < INF) ? W1n[k * HID + hs] : 0.f;
        __nv_bfloat16 h = __float2bfloat16_rn(v);
        blob[idx] = h;
        blob[W1T + idx] = __float2bfloat16_rn(v - __bfloat162float(h));
    }
    const int base2 = 2 * W1T;
    for (int idx = tid; idx < W2T; idx += 256) {
        int k = idx / WS, hs = idx % WS;
        float v = (hs < HID) ? W2n[k * HID + hs] : 0.f;
        __nv_bfloat16 h = __float2bfloat16_rn(v);
        blob[base2 + idx] = h;
        blob[base2 + W2T + idx] = __float2bfloat16_rn(v - __bfloat162float(h));
    }
    const int base3 = 2 * W1T + 2 * W2T;
    for (int idx = tid; idx < W3T; idx += 256) {
        int k = idx >> 3, o = idx & 7;
        float v = (o < 4) ? W3n[k * 4 + o] : 0.f;
        __nv_bfloat16 h = __float2bfloat16_rn(v);
        blob[base3 + idx] = h;
        blob[base3 + W3T + idx] = __float2bfloat16_rn(v - __bfloat162float(h));
    }
    if (tid < 128) {
        g_bias[net][tid]       = b1[net * HID + tid];
        g_bias[net][128 + tid] = b2[net * HID + tid];
    }
    if (tid < 8) g_bias[net][256 + tid] = (tid < 4) ? b3[net * 4 + tid] : 0.f;
}

// ---------------------------------------------------------------------------
// Kernel 1: per-ray block (128 threads = 128 samples of one ray).
// Writes X directly as split-bf16 [t][80] (smem-staged, coalesced) + splits.
// ---------------------------------------------------------------------------
__global__ __launch_bounds__(128)
void k_features(const float* __restrict__ ro,
                const float* __restrict__ rd,
                const float* __restrict__ Ws,
                const float* __restrict__ bsv,
                float* __restrict__ splits_out) {
    __shared__ __nv_bfloat16 sHi[128 * 80];
    __shared__ __nv_bfloat16 sLo[128 * 80];
    int tid = threadIdx.x;
    int bray = blockIdx.x;
    int t0 = bray * P_PTS;
    int t = t0 + tid;

    float tp = g_t[tid];
    float o0 = ro[bray * 3 + 0], o1 = ro[bray * 3 + 1], o2 = ro[bray * 3 + 2];
    float d0 = rd[bray * 3 + 0], d1 = rd[bray * 3 + 1], d2 = rd[bray * 3 + 2];
    float r0 = __fadd_rn(__fmul_rn(d0, tp), o0);
    float r1 = __fadd_rn(__fmul_rn(d1, tp), o1);
    float r2 = __fadd_rn(__fmul_rn(d2, tp), o2);

    __nv_bfloat16* rowh = &sHi[tid * 80];
    __nv_bfloat16* rowl = &sLo[tid * 80];
#define PUT(f, v) { float _v = (v); __nv_bfloat16 _h = __float2bfloat16_rn(_v); \
                    rowh[f] = _h; rowl[f] = __float2bfloat16_rn(_v - __bfloat162float(_h)); }
    PUT(0, r0) PUT(1, r1) PUT(2, r2)

    const float pif = 3.14159274101257324f;  // float(np.pi)
    float rc[3] = {r0, r1, r2};
#pragma unroll
    for (int c = 0; c < 3; ++c) {
        double a = (double)__fmul_rn(rc[c], pif);
        double s, co;
        sincos_acc(a, &s, &co);
#pragma unroll
        for (int l = 0; l < LFREQ; ++l) {
            PUT(3 + 6 * l + c,     (float)co)
            PUT(3 + 6 * l + 3 + c, (float)s)
            double sc = s * co;
            double cc = co * co;
            s  = sc + sc;
            co = __fma_rn(2.0, cc, -1.0);
        }
    }
    PUT(63, d0) PUT(64, d1) PUT(65, d2)
#pragma unroll
    for (int f = 66; f < 80; ++f) { rowh[f] = __float2bfloat16_rn(0.f); rowl[f] = rowh[f]; }
#undef PUT

    // splits = softmax(ray @ Ws + bs)
    float lg[NNET];
#pragma unroll
    for (int n = 0; n < NNET; ++n)
        lg[n] = bsv[n] + r0 * Ws[0 * NNET + n] + r1 * Ws[1 * NNET + n] + r2 * Ws[2 * NNET + n];
    float mx = lg[0];
#pragma unroll
    for (int n = 1; n < NNET; ++n) mx = fmaxf(mx, lg[n]);
    float sum = 0.f;
    float e[NNET];
#pragma unroll
    for (int n = 0; n < NNET; ++n) { e[n] = expf(lg[n] - mx); sum += e[n]; }
    float inv = __fdiv_rn(1.0f, sum);
#pragma unroll
    for (int n = 0; n < NNET; ++n) splits_out[t * NNET + n] = e[n] * inv;

    __syncthreads();
    // coalesced flush: 128*80 bf16 = 1280 uint4 per array
    const uint4* s4h = (const uint4*)sHi;
    const uint4* s4l = (const uint4*)sLo;
    uint4* g4h = (uint4*)(g_Xhi + (size_t)t0 * 80);
    uint4* g4l = (uint4*)(g_Xlo + (size_t)t0 * 80);
    for (int i = tid; i < 1280; i += 128) {
        g4h[i] = s4h[i];
        g4l[i] = s4l[i];
    }
}

// ---------------------------------------------------------------------------
// Tensor-core MLP (persistent over 8 tiles, cp.async double-buffered X)
// ---------------------------------------------------------------------------
__device__ __forceinline__ unsigned sptr(const void* p) {
    return (unsigned)__cvta_generic_to_shared(p);
}
__device__ __forceinline__ void cpa16(unsigned dst, const void* src) {
    asm volatile("cp.async.cg.shared.global [%0], [%1], 16;" :: "r"(dst), "l"(src));
}
__device__ __forceinline__ void cpa_commit() {
    asm volatile("cp.async.commit_group;");
}
__device__ __forceinline__ void cpa_wait0() {
    asm volatile("cp.async.wait_group 0;");
}
__device__ __forceinline__ void ldsm4(unsigned a, unsigned& r0, unsigned& r1,
                                      unsigned& r2, unsigned& r3) {
    asm volatile("ldmatrix.sync.aligned.m8n8.x4.shared.b16 {%0,%1,%2,%3}, [%4];"
                 : "=r"(r0), "=r"(r1), "=r"(r2), "=r"(r3) : "r"(a));
}
__device__ __forceinline__ void ldsm4t(unsigned a, unsigned& r0, unsigned& r1,
                                       unsigned& r2, unsigned& r3) {
    asm volatile("ldmatrix.sync.aligned.m8n8.x4.trans.shared.b16 {%0,%1,%2,%3}, [%4];"
                 : "=r"(r0), "=r"(r1), "=r"(r2), "=r"(r3) : "r"(a));
}
__device__ __forceinline__ void ldsm2t(unsigned a, unsigned& r0, unsigned& r1) {
    asm volatile("ldmatrix.sync.aligned.m8n8.x2.trans.shared.b16 {%0,%1}, [%2];"
                 : "=r"(r0), "=r"(r1) : "r"(a));
}
__device__ __forceinline__ void mma_bf16(float* d, const unsigned* a, unsigned b0, unsigned b1) {
    asm volatile("mma.sync.aligned.m16n8k16.row.col.f32.bf16.bf16.f32 "
                 "{%0,%1,%2,%3}, {%4,%5,%6,%7}, {%8,%9}, {%0,%1,%2,%3};"
                 : "+f"(d[0]), "+f"(d[1]), "+f"(d[2]), "+f"(d[3])
                 : "r"(a[0]), "r"(a[1]), "r"(a[2]), "r"(a[3]), "r"(b0), "r"(b1));
}
__device__ __forceinline__ unsigned packsplit(float v0, float v1, unsigned& lo) {
    __nv_bfloat16 h0 = __float2bfloat16_rn(v0);
    __nv_bfloat16 h1 = __float2bfloat16_rn(v1);
    __nv_bfloat16 l0 = __float2bfloat16_rn(v0 - __bfloat162float(h0));
    __nv_bfloat16 l1 = __float2bfloat16_rn(v1 - __bfloat162float(h1));
    lo = (unsigned)__bfloat16_as_ushort(l0) | ((unsigned)__bfloat16_as_ushort(l1) << 16);
    return (unsigned)__bfloat16_as_ushort(h0) | ((unsigned)__bfloat16_as_ushort(h1) << 16);
}

extern __shared__ char smemc[];

__global__ __launch_bounds__(256, 1)
void k_mlp() {
    const int tid  = threadIdx.x;
    const int lane = tid & 31;
    const int warp = tid >> 5;
    const int net  = blockIdx.y;

    const unsigned sbase = sptr(smemc);
    float* sb1 = (float*)(smemc + OFF_B);
    float* sb2 = (float*)(smemc + OFF_B + 512);
    float* sb3 = (float*)(smemc + OFF_B + 1024);

    // ---- one-time weight + bias blob copy (async) ----
    {
        const char* wsrc = (const char*)g_wblob[net];
        for (int i = tid * 16; i < BLOB_BYTES; i += 256 * 16)
            cpa16(sbase + OFF_W + i, wsrc + i);
        const char* bsrc = (const char*)g_bias[net];
        if (tid * 16 < 1056)
            cpa16(sbase + OFF_B + tid * 16, bsrc + tid * 16);
    }
    // ---- first X tile copy ----
    {
        int t0 = blockIdx.x * 128;
        for (int c = tid; c < 1280; c += 256) {
            int m = c / 10, cc = c - m * 10;
            unsigned d = sbase + OFF_X0 + (m * XS + cc * 8) * 2;
            size_t gsrc = (size_t)(t0 + m) * 80 + cc * 8;
            cpa16(d,         g_Xhi + gsrc);
            cpa16(d + 22528, g_Xlo + gsrc);
        }
    }
    cpa_commit();

    // ---- per-warp fragment geometry ----
    const int m0   = warp * 16;
    const int lrow = lane & 15;
    const int lch  = lane >> 4;
    const int cb   = (lane & 3) * 2;

    const unsigned aW1hi = sbase + OFF_W + B_W1HI + (lrow * WS + lch * 8) * 2;
    const unsigned aW1lo = sbase + OFF_W + B_W1LO + (lrow * WS + lch * 8) * 2;
    const unsigned aW2hi = sbase + OFF_W + B_W2HI + (lrow * WS + lch * 8) * 2;
    const unsigned aW2lo = sbase + OFF_W + B_W2LO + (lrow * WS + lch * 8) * 2;
    const unsigned aW3hi = sbase + OFF_W + B_W3HI + (lrow * 8) * 2;
    const unsigned aW3lo = sbase + OFF_W + B_W3LO + (lrow * 8) * 2;

    for (int it = 0; it < TILES_PER_BLOCK; ++it) {
        const int t0 = (blockIdx.x + GX * it) * 128;
        const unsigned xoff = (it & 1) ? OFF_X1 : OFF_X0;

        cpa_wait0();
        __syncthreads();

        // prefetch next tile into the other buffer
        if (it + 1 < TILES_PER_BLOCK) {
            int tn0 = (blockIdx.x + GX * (it + 1)) * 128;
            unsigned nxoff = ((it + 1) & 1) ? OFF_X1 : OFF_X0;
            for (int c = tid; c < 1280; c += 256) {
                int m = c / 10, cc = c - m * 10;
                unsigned d = sbase + nxoff + (m * XS + cc * 8) * 2;
                size_t gsrc = (size_t)(tn0 + m) * 80 + cc * 8;
                cpa16(d,         g_Xhi + gsrc);
                cpa16(d + 22528, g_Xlo + gsrc);
            }
            cpa_commit();
        }

        const unsigned aXhi = sbase + xoff + ((m0 + lrow) * XS + lch * 8) * 2;
        const unsigned aXlo = aXhi + 22528;

        // ============================ layer 1 ============================
        float acc[16][4];
#pragma unroll
        for (int j = 0; j < 16; ++j) {
            float bv0 = sb1[j * 8 + cb], bv1 = sb1[j * 8 + cb + 1];
            acc[j][0] = bv0; acc[j][1] = bv1; acc[j][2] = bv0; acc[j][3] = bv1;
        }
#pragma unroll
        for (int ks = 0; ks < KPAD1 / 16; ++ks) {
            unsigned ah[4], al[4];
            ldsm4(aXhi + ks * 32, ah[0], ah[1], ah[2], ah[3]);
            ldsm4(aXlo + ks * 32, al[0], al[1], al[2], al[3]);
#pragma unroll
            for (int jp = 0; jp < 8; ++jp) {
                unsigned bh0, bh1, bh2, bh3, bl0, bl1, bl2, bl3;
                ldsm4t(aW1hi + (ks * 16 * WS + jp * 16) * 2, bh0, bh1, bh2, bh3);
                ldsm4t(aW1lo + (ks * 16 * WS + jp * 16) * 2, bl0, bl1, bl2, bl3);
                mma_bf16(acc[2 * jp],     ah, bh0, bh1);
                mma_bf16(acc[2 * jp],     ah, bl0, bl1);
                mma_bf16(acc[2 * jp],     al, bh0, bh1);
                mma_bf16(acc[2 * jp + 1], ah, bh2, bh3);
                mma_bf16(acc[2 * jp + 1], ah, bl2, bl3);
                mma_bf16(acc[2 * jp + 1], al, bh2, bh3);
            }
        }
        unsigned a2h[8][4], a2l[8][4];
#pragma unroll
        for (int kk = 0; kk < 8; ++kk) {
#pragma unroll
            for (int half = 0; half < 2; ++half) {
                int j = 2 * kk + half;
                float v0 = fmaxf(acc[j][0], 0.f), v1 = fmaxf(acc[j][1], 0.f);
                float v2 = fmaxf(acc[j][2], 0.f), v3 = fmaxf(acc[j][3], 0.f);
                a2h[kk][2 * half]     = packsplit(v0, v1, a2l[kk][2 * half]);
                a2h[kk][2 * half + 1] = packsplit(v2, v3, a2l[kk][2 * half + 1]);
            }
        }

        // ============================ layer 2 ============================
        float acc2[16][4];
#pragma unroll
        for (int j = 0; j < 16; ++j) {
            float bv0 = sb2[j * 8 + cb], bv1 = sb2[j * 8 + cb + 1];
            acc2[j][0] = bv0; acc2[j][1] = bv1; acc2[j][2] = bv0; acc2[j][3] = bv1;
        }
#pragma unroll
        for (int kk = 0; kk < 8; ++kk) {
#pragma unroll
            for (int jp = 0; jp < 8; ++jp) {
                unsigned bh0, bh1, bh2, bh3, bl0, bl1, bl2, bl3;
                ldsm4t(aW2hi + (kk * 16 * WS + jp * 16) * 2, bh0, bh1, bh2, bh3);
                ldsm4t(aW2lo + (kk * 16 * WS + jp * 16) * 2, bl0, bl1, bl2, bl3);
                mma_bf16(acc2[2 * jp],     a2h[kk], bh0, bh1);
                mma_bf16(acc2[2 * jp],     a2h[kk], bl0, bl1);
                mma_bf16(acc2[2 * jp],     a2l[kk], bh0, bh1);
                mma_bf16(acc2[2 * jp + 1], a2h[kk], bh2, bh3);
                mma_bf16(acc2[2 * jp + 1], a2h[kk], bl2, bl3);
                mma_bf16(acc2[2 * jp + 1], a2l[kk], bh2, bh3);
            }
        }
        unsigned a3h[8][4], a3l[8][4];
#pragma unroll
        for (int kk = 0; kk < 8; ++kk) {
#pragma unroll
            for (int half = 0; half < 2; ++half) {
                int j = 2 * kk + half;
                float v0 = fmaxf(acc2[j][0], 0.f), v1 = fmaxf(acc2[j][1], 0.f);
                float v2 = fmaxf(acc2[j][2], 0.f), v3 = fmaxf(acc2[j][3], 0.f);
                a3h[kk][2 * half]     = packsplit(v0, v1, a3l[kk][2 * half]);
                a3h[kk][2 * half + 1] = packsplit(v2, v3, a3l[kk][2 * half + 1]);
            }
        }

        // ============================ layer 3 ============================
        float acc3[4];
        acc3[0] = sb3[cb]; acc3[1] = sb3[cb + 1]; acc3[2] = acc3[0]; acc3[3] = acc3[1];
#pragma unroll
        for (int kk = 0; kk < 8; ++kk) {
            unsigned bh0, bh1, bl0, bl1;
            ldsm2t(aW3hi + (kk * 16 * 8) * 2, bh0, bh1);
            ldsm2t(aW3lo + (kk * 16 * 8) * 2, bl0, bl1);
            mma_bf16(acc3, a3h[kk], bh0, bh1);
            mma_bf16(acc3, a3h[kk], bl0, bl1);
            mma_bf16(acc3, a3l[kk], bh0, bh1);
        }

        if ((lane & 3) < 2) {
            int row = t0 + m0 + (lane >> 2);
            long base = ((long)net * TOK + row) * 4 + cb;
            *(float2*)&g_ev[base] = make_float2(acc3[0], acc3[1]);
            base = ((long)net * TOK + row + 8) * 4 + cb;
            *(float2*)&g_ev[base] = make_float2(acc3[2], acc3[3]);
        }
    }
}

// ---------------------------------------------------------------------------
// Kernel 3: combine nets with splits, volume-render per ray
// ---------------------------------------------------------------------------
__global__ void k_render(float* __restrict__ out) {
    const float* splits = out + BATCH * 3;
    __shared__ float s_scan[P_PTS];
    __shared__ float s_red[P_PTS];
    int b = blockIdx.x;
    int p = threadIdx.x;
    int t = b * P_PTS + p;

    float sp[NNET];
#pragma unroll
    for (int n = 0; n < NNET; ++n) sp[n] = splits[t * NNET + n];

    float ne0 = 0.f, ne1 = 0.f, ne2 = 0.f, ne3 = 0.f;
#pragma unroll
    for (int n = 0; n < NNET; ++n) {
        long base = ((long)n * TOK + t) * 4;
        ne0 = fmaf(g_ev[base + 0], sp[n], ne0);
        ne1 = fmaf(g_ev[base + 1], sp[n], ne1);
        ne2 = fmaf(g_ev[base + 2], sp[n], ne2);
        ne3 = fmaf(g_ev[base + 3], sp[n], ne3);
    }

    float diff = (p < 127) ? g_diffs[p] : 0.f;
    float sd = ne3 * diff;

    s_scan[p] = sd;
    __syncthreads();
#pragma unroll
    for (int off = 1; off < P_PTS; off <<= 1) {
        float v = (p >= off) ? s_scan[p - off] : 0.f;
        __syncthreads();
        s_scan[p] += v;
        __syncthreads();
    }
    float T = expf(s_scan[p]);
    float w = (p < 127) ? T * (1.0f - expf(-sd)) : 0.f;

    float col[3] = {w * ne0, w * ne1, w * ne2};
#pragma unroll
    for (int c = 0; c < 3; ++c) {
        s_red[p] = col[c];
        __syncthreads();
        for (int off = 64; off >= 1; off >>= 1) {
            if (p < off) s_red[p] += s_red[p + off];
            __syncthreads();
        }
        if (p == 0) out[b * 3 + c] = s_red[0];
        __syncthreads();
    }
}

// ---------------------------------------------------------------------------
// Launch
// ---------------------------------------------------------------------------
extern "C" void kernel_launch(void* const* d_in, const int* in_sizes, int n_in,
                              void* d_out, int out_size) {
    const float* ray_o = (const float*)d_in[0];
    const float* ray_d = (const float*)d_in[1];
    const float* s_st  = (const float*)d_in[2];
    const float* s_en  = (const float*)d_in[3];
    // d_in[4] = num_integration_points (hardcoded 128)
    const float* W1 = (const float*)d_in[5];
    const float* b1 = (const float*)d_in[6];
    const float* W2 = (const float*)d_in[7];
    const float* b2 = (const float*)d_in[8];
    const float* W3 = (const float*)d_in[9];
    const float* b3 = (const float*)d_in[10];
    const float* Ws = (const float*)d_in[11];
    const float* bs = (const float*)d_in[12];
    float* out = (float*)d_out;

    cudaFuncSetAttribute(k_mlp, cudaFuncAttributeMaxDynamicSharedMemorySize, SMEM_BYTES);

    k_init<<<1, 128>>>(s_st, s_en);
    k_prep<<<NNET, 256>>>(W1, b1, W2, b2, W3, b3);
    k_features<<<BATCH, 128>>>(ray_o, ray_d, Ws, bs, out + BATCH * 3);
    dim3 grid(GX, NNET);
    k_mlp<<<grid, 256, SMEM_BYTES>>>();
    k_render<<<BATCH, P_PTS>>>(out);
}

// round 11
// speedup vs baseline: 3.8751x; 1.2769x over previous
#include <cuda_runtime.h>
#include <cuda_fp16.h>
#include <math.h>

// ---------------------------------------------------------------------------
// Problem constants
// ---------------------------------------------------------------------------
#define BATCH 1024
#define P_PTS 128
#define TOK   (BATCH * P_PTS)     // 131072 tokens
#define NNET  8
#define HID   128
#define INF   66                   // IN_DIM = 6*10+6
#define KPAD1 80                   // layer-1 K padded to multiple of 16
#define LFREQ 10

// strides (fp16 elems): odd multiples of 8 -> conflict-free ldmatrix
#define XS  88     // X^T rows [128 tok][88]
#define WS  136    // W1/W2 rows [k][136]

#define W1T (KPAD1 * WS)   // 10880 elems
#define W2T (128 * WS)     // 17408
#define W3T (128 * 8)      // 1024
// blob byte offsets (single fp16 weights — no lo terms)
#define B_W1 0
#define B_W2 (B_W1 + W1T * 2)       // 21760
#define B_W3 (B_W2 + W2T * 2)       // 56576
#define BLOB_BYTES (B_W3 + W3T * 2) // 58624

// k_mlp smem layout (bytes)
#define OFF_W   0
#define OFF_B   BLOB_BYTES              // 58624 : b1[128] b2[128] b3[8] floats
#define OFF_X0  (OFF_B + 1056)          // 59680
#define XBUF_BYTES 45056                // hi 22528 + lo 22528
#define OFF_X1  (OFF_X0 + XBUF_BYTES)   // 104736
#define SMEM_BYTES (OFF_X1 + XBUF_BYTES) // 149792

#define GX 128                          // blocks per net
#define TILES_PER_BLOCK (1024 / GX)     // 8

// ---------------------------------------------------------------------------
// Device scratch
// ---------------------------------------------------------------------------
__device__ float g_t[P_PTS];
__device__ float g_diffs[P_PTS - 1];
__device__ __align__(16) __half g_Xhi[TOK * 80];  // [t][80] row-major
__device__ __align__(16) __half g_Xlo[TOK * 80];
__device__ __align__(16) __half g_wblob[NNET][BLOB_BYTES / 2];
__device__ __align__(16) float g_bias[NNET][264];  // b1,b2,b3pad
__device__ float g_ev[NNET * TOK * 4];

// ---------------------------------------------------------------------------
// Accurate sincos (double precision; immune to --use_fast_math rewrites).
// ---------------------------------------------------------------------------
__device__ __forceinline__ void sincos_acc(double x, double* sp, double* cp) {
    int k = __double2int_rn(x * 0.63661977236758138);
    double q = (double)k;
    double r = __fma_rn(q, -1.5707963267948966, x);
    r = __fma_rn(q, -6.123233995736766e-17, r);
    double r2 = r * r;
    double s = __fma_rn(r2, 2.7557319223985893e-06, -1.9841269841269841e-04);
    s = __fma_rn(r2, s, 8.3333333333333332e-03);
    s = __fma_rn(r2, s, -1.6666666666666666e-01);
    s = __fma_rn(r * r2, s, r);
    double c = __fma_rn(r2, -2.7557319223985888e-07, 2.4801587301587302e-05);
    c = __fma_rn(r2, c, -1.3888888888888889e-03);
    c = __fma_rn(r2, c, 4.1666666666666664e-02);
    c = __fma_rn(r2, c, -0.5);
    c = __fma_rn(r2, c, 1.0);
    switch (k & 3) {
        case 0: *sp = s;  *cp = c;  break;
        case 1: *sp = c;  *cp = -s; break;
        case 2: *sp = -s; *cp = -c; break;
        default:*sp = -c; *cp = s;  break;
    }
}

// ---------------------------------------------------------------------------
// Kernel 0: jax partitionable threefry, key (0,42); bits = y0 ^ y1
// ---------------------------------------------------------------------------
__global__ void k_init(const float* __restrict__ sstart,
                       const float* __restrict__ send) {
    __shared__ float st[P_PTS];
    int i = threadIdx.x;
    float start = *sstart, end = *send;
    {
        unsigned x0 = 0u;
        unsigned x1 = (unsigned)i;
        const unsigned ks0 = 0u;
        const unsigned ks1 = 42u;
        const unsigned ks2 = 0x1BD11BDAu ^ 0u ^ 42u;
        x0 += ks0; x1 += ks1;
#define TF_R(r) { x0 += x1; x1 = (x1 << (r)) | (x1 >> (32 - (r))); x1 ^= x0; }
        TF_R(13) TF_R(15) TF_R(26) TF_R(6)
        x0 += ks1; x1 += ks2 + 1u;
        TF_R(17) TF_R(29) TF_R(16) TF_R(24)
        x0 += ks2; x1 += ks0 + 2u;
        TF_R(13) TF_R(15) TF_R(26) TF_R(6)
        x0 += ks0; x1 += ks1 + 3u;
        TF_R(17) TF_R(29) TF_R(16) TF_R(24)
        x0 += ks1; x1 += ks2 + 4u;
        TF_R(13) TF_R(15) TF_R(26) TF_R(6)
        x0 += ks2; x1 += ks0 + 5u;
#undef TF_R
        unsigned bits = x0 ^ x1;
        float u = __uint_as_float((bits >> 9) | 0x3f800000u) - 1.0f;
        float range = __fadd_rn(end, -start);
        float step  = __fdiv_rn(range, 127.0f);
        float basev = __fadd_rn(start, __fmul_rn((float)i, step));
        float tv    = __fadd_rn(basev, __fdiv_rn(__fmul_rn(u, range), 127.0f));
        st[i] = tv;
        g_t[i] = tv;
    }
    __syncthreads();
    if (i < 127) g_diffs[i] = __fadd_rn(st[i + 1], -st[i]);
}

// ---------------------------------------------------------------------------
// Kernel P: weights -> single-fp16 blobs in smem-tile layout (once per net)
// ---------------------------------------------------------------------------
__global__ void k_prep(const float* __restrict__ W1, const float* __restrict__ b1,
                       const float* __restrict__ W2, const float* __restrict__ b2,
                       const float* __restrict__ W3, const float* __restrict__ b3) {
    int net = blockIdx.x;
    int tid = threadIdx.x;
    __half* blob = g_wblob[net];
    const float* W1n = W1 + net * INF * HID;
    const float* W2n = W2 + net * HID * HID;
    const float* W3n = W3 + net * HID * 4;

    for (int idx = tid; idx < W1T; idx += 256) {
        int k = idx / WS, hs = idx % WS;
        float v = (hs < HID && k < INF) ? W1n[k * HID + hs] : 0.f;
        blob[idx] = __float2half_rn(v);
    }
    const int base2 = W1T;
    for (int idx = tid; idx < W2T; idx += 256) {
        int k = idx / WS, hs = idx % WS;
        float v = (hs < HID) ? W2n[k * HID + hs] : 0.f;
        blob[base2 + idx] = __float2half_rn(v);
    }
    const int base3 = W1T + W2T;
    for (int idx = tid; idx < W3T; idx += 256) {
        int k = idx >> 3, o = idx & 7;
        float v = (o < 4) ? W3n[k * 4 + o] : 0.f;
        blob[base3 + idx] = __float2half_rn(v);
    }
    if (tid < 128) {
        g_bias[net][tid]       = b1[net * HID + tid];
        g_bias[net][128 + tid] = b2[net * HID + tid];
    }
    if (tid < 8) g_bias[net][256 + tid] = (tid < 4) ? b3[net * 4 + tid] : 0.f;
}

// ---------------------------------------------------------------------------
// Kernel 1: per-ray block; X written as 2-term fp16 split [t][80] + splits.
// ---------------------------------------------------------------------------
__global__ __launch_bounds__(128)
void k_features(const float* __restrict__ ro,
                const float* __restrict__ rd,
                const float* __restrict__ Ws,
                const float* __restrict__ bsv,
                float* __restrict__ splits_out) {
    __shared__ __half sHi[128 * 80];
    __shared__ __half sLo[128 * 80];
    int tid = threadIdx.x;
    int bray = blockIdx.x;
    int t0 = bray * P_PTS;
    int t = t0 + tid;

    float tp = g_t[tid];
    float o0 = ro[bray * 3 + 0], o1 = ro[bray * 3 + 1], o2 = ro[bray * 3 + 2];
    float d0 = rd[bray * 3 + 0], d1 = rd[bray * 3 + 1], d2 = rd[bray * 3 + 2];
    float r0 = __fadd_rn(__fmul_rn(d0, tp), o0);
    float r1 = __fadd_rn(__fmul_rn(d1, tp), o1);
    float r2 = __fadd_rn(__fmul_rn(d2, tp), o2);

    __half* rowh = &sHi[tid * 80];
    __half* rowl = &sLo[tid * 80];
#define PUT(f, v) { float _v = (v); __half _h = __float2half_rn(_v); \
                    rowh[f] = _h; rowl[f] = __float2half_rn(_v - __half2float(_h)); }
    PUT(0, r0) PUT(1, r1) PUT(2, r2)

    const float pif = 3.14159274101257324f;  // float(np.pi)
    float rc[3] = {r0, r1, r2};
#pragma unroll
    for (int c = 0; c < 3; ++c) {
        double a = (double)__fmul_rn(rc[c], pif);
        double s, co;
        sincos_acc(a, &s, &co);
#pragma unroll
        for (int l = 0; l < LFREQ; ++l) {
            PUT(3 + 6 * l + c,     (float)co)
            PUT(3 + 6 * l + 3 + c, (float)s)
            double sc = s * co;
            double cc = co * co;
            s  = sc + sc;
            co = __fma_rn(2.0, cc, -1.0);
        }
    }
    PUT(63, d0) PUT(64, d1) PUT(65, d2)
#pragma unroll
    for (int f = 66; f < 80; ++f) { rowh[f] = __float2half_rn(0.f); rowl[f] = rowh[f]; }
#undef PUT

    float lg[NNET];
#pragma unroll
    for (int n = 0; n < NNET; ++n)
        lg[n] = bsv[n] + r0 * Ws[0 * NNET + n] + r1 * Ws[1 * NNET + n] + r2 * Ws[2 * NNET + n];
    float mx = lg[0];
#pragma unroll
    for (int n = 1; n < NNET; ++n) mx = fmaxf(mx, lg[n]);
    float sum = 0.f;
    float e[NNET];
#pragma unroll
    for (int n = 0; n < NNET; ++n) { e[n] = expf(lg[n] - mx); sum += e[n]; }
    float inv = __fdiv_rn(1.0f, sum);
#pragma unroll
    for (int n = 0; n < NNET; ++n) splits_out[t * NNET + n] = e[n] * inv;

    __syncthreads();
    const uint4* s4h = (const uint4*)sHi;
    const uint4* s4l = (const uint4*)sLo;
    uint4* g4h = (uint4*)(g_Xhi + (size_t)t0 * 80);
    uint4* g4l = (uint4*)(g_Xlo + (size_t)t0 * 80);
    for (int i = tid; i < 1280; i += 128) {
        g4h[i] = s4h[i];
        g4l[i] = s4l[i];
    }
}

// ---------------------------------------------------------------------------
// Tensor-core MLP: mma.sync m16n8k16 fp16, 2-term activation split, single
// fp16 weights. Persistent over 8 tiles, cp.async double-buffered X.
// ---------------------------------------------------------------------------
__device__ __forceinline__ unsigned sptr(const void* p) {
    return (unsigned)__cvta_generic_to_shared(p);
}
__device__ __forceinline__ void cpa16(unsigned dst, const void* src) {
    asm volatile("cp.async.cg.shared.global [%0], [%1], 16;" :: "r"(dst), "l"(src));
}
__device__ __forceinline__ void cpa_commit() { asm volatile("cp.async.commit_group;"); }
__device__ __forceinline__ void cpa_wait0()  { asm volatile("cp.async.wait_group 0;"); }
__device__ __forceinline__ void ldsm4(unsigned a, unsigned& r0, unsigned& r1,
                                      unsigned& r2, unsigned& r3) {
    asm volatile("ldmatrix.sync.aligned.m8n8.x4.shared.b16 {%0,%1,%2,%3}, [%4];"
                 : "=r"(r0), "=r"(r1), "=r"(r2), "=r"(r3) : "r"(a));
}
__device__ __forceinline__ void ldsm4t(unsigned a, unsigned& r0, unsigned& r1,
                                       unsigned& r2, unsigned& r3) {
    asm volatile("ldmatrix.sync.aligned.m8n8.x4.trans.shared.b16 {%0,%1,%2,%3}, [%4];"
                 : "=r"(r0), "=r"(r1), "=r"(r2), "=r"(r3) : "r"(a));
}
__device__ __forceinline__ void ldsm2t(unsigned a, unsigned& r0, unsigned& r1) {
    asm volatile("ldmatrix.sync.aligned.m8n8.x2.trans.shared.b16 {%0,%1}, [%2];"
                 : "=r"(r0), "=r"(r1) : "r"(a));
}
__device__ __forceinline__ void mma_f16(float* d, const unsigned* a, unsigned b0, unsigned b1) {
    asm volatile("mma.sync.aligned.m16n8k16.row.col.f32.f16.f16.f32 "
                 "{%0,%1,%2,%3}, {%4,%5,%6,%7}, {%8,%9}, {%0,%1,%2,%3};"
                 : "+f"(d[0]), "+f"(d[1]), "+f"(d[2]), "+f"(d[3])
                 : "r"(a[0]), "r"(a[1]), "r"(a[2]), "r"(a[3]), "r"(b0), "r"(b1));
}
// split-pack two fp32 into fp16x2 (hi) and residual fp16x2 (lo)
__device__ __forceinline__ unsigned packsplit(float v0, float v1, unsigned& lo) {
    __half h0 = __float2half_rn(v0);
    __half h1 = __float2half_rn(v1);
    __half l0 = __float2half_rn(v0 - __half2float(h0));
    __half l1 = __float2half_rn(v1 - __half2float(h1));
    lo = (unsigned)__half_as_ushort(l0) | ((unsigned)__half_as_ushort(l1) << 16);
    return (unsigned)__half_as_ushort(h0) | ((unsigned)__half_as_ushort(h1) << 16);
}

extern __shared__ char smemc[];

__global__ __launch_bounds__(256, 1)
void k_mlp() {
    const int tid  = threadIdx.x;
    const int lane = tid & 31;
    const int warp = tid >> 5;
    const int net  = blockIdx.y;

    const unsigned sbase = sptr(smemc);
    float* sb1 = (float*)(smemc + OFF_B);
    float* sb2 = (float*)(smemc + OFF_B + 512);
    float* sb3 = (float*)(smemc + OFF_B + 1024);

    // ---- one-time weight + bias blob copy (async) ----
    {
        const char* wsrc = (const char*)g_wblob[net];
        for (int i = tid * 16; i < BLOB_BYTES; i += 256 * 16)
            cpa16(sbase + OFF_W + i, wsrc + i);
        const char* bsrc = (const char*)g_bias[net];
        if (tid * 16 < 1056)
            cpa16(sbase + OFF_B + tid * 16, bsrc + tid * 16);
    }
    // ---- first X tile copy ----
    {
        int t0 = blockIdx.x * 128;
        for (int c = tid; c < 1280; c += 256) {
            int m = c / 10, cc = c - m * 10;
            unsigned d = sbase + OFF_X0 + (m * XS + cc * 8) * 2;
            size_t gsrc = (size_t)(t0 + m) * 80 + cc * 8;
            cpa16(d,         g_Xhi + gsrc);
            cpa16(d + 22528, g_Xlo + gsrc);
        }
    }
    cpa_commit();

    // ---- per-warp fragment geometry ----
    const int m0   = warp * 16;
    const int lrow = lane & 15;
    const int lch  = lane >> 4;
    const int cb   = (lane & 3) * 2;

    const unsigned aW1 = sbase + OFF_W + B_W1 + (lrow * WS + lch * 8) * 2;
    const unsigned aW2 = sbase + OFF_W + B_W2 + (lrow * WS + lch * 8) * 2;
    const unsigned aW3 = sbase + OFF_W + B_W3 + (lrow * 8) * 2;

    for (int it = 0; it < TILES_PER_BLOCK; ++it) {
        const int t0 = (blockIdx.x + GX * it) * 128;
        const unsigned xoff = (it & 1) ? OFF_X1 : OFF_X0;

        cpa_wait0();
        __syncthreads();

        // prefetch next tile into the other buffer
        if (it + 1 < TILES_PER_BLOCK) {
            int tn0 = (blockIdx.x + GX * (it + 1)) * 128;
            unsigned nxoff = ((it + 1) & 1) ? OFF_X1 : OFF_X0;
            for (int c = tid; c < 1280; c += 256) {
                int m = c / 10, cc = c - m * 10;
                unsigned d = sbase + nxoff + (m * XS + cc * 8) * 2;
                size_t gsrc = (size_t)(tn0 + m) * 80 + cc * 8;
                cpa16(d,         g_Xhi + gsrc);
                cpa16(d + 22528, g_Xlo + gsrc);
            }
            cpa_commit();
        }

        const unsigned aXhi = sbase + xoff + ((m0 + lrow) * XS + lch * 8) * 2;
        const unsigned aXlo = aXhi + 22528;

        // ============================ layer 1 ============================
        float acc[16][4];
#pragma unroll
        for (int j = 0; j < 16; ++j) {
            float bv0 = sb1[j * 8 + cb], bv1 = sb1[j * 8 + cb + 1];
            acc[j][0] = bv0; acc[j][1] = bv1; acc[j][2] = bv0; acc[j][3] = bv1;
        }
#pragma unroll
        for (int ks = 0; ks < KPAD1 / 16; ++ks) {
            unsigned ah[4], al[4];
            ldsm4(aXhi + ks * 32, ah[0], ah[1], ah[2], ah[3]);
            ldsm4(aXlo + ks * 32, al[0], al[1], al[2], al[3]);
#pragma unroll
            for (int jp = 0; jp < 8; ++jp) {
                unsigned b0, b1, b2, b3;
                ldsm4t(aW1 + (ks * 16 * WS + jp * 16) * 2, b0, b1, b2, b3);
                mma_f16(acc[2 * jp],     ah, b0, b1);
                mma_f16(acc[2 * jp + 1], ah, b2, b3);
                mma_f16(acc[2 * jp],     al, b0, b1);
                mma_f16(acc[2 * jp + 1], al, b2, b3);
            }
        }
        // relu + repack C frags -> layer-2 A frags (registers only)
        unsigned a2h[8][4], a2l[8][4];
#pragma unroll
        for (int kk = 0; kk < 8; ++kk) {
#pragma unroll
            for (int half = 0; half < 2; ++half) {
                int j = 2 * kk + half;
                float v0 = fmaxf(acc[j][0], 0.f), v1 = fmaxf(acc[j][1], 0.f);
                float v2 = fmaxf(acc[j][2], 0.f), v3 = fmaxf(acc[j][3], 0.f);
                a2h[kk][2 * half]     = packsplit(v0, v1, a2l[kk][2 * half]);
                a2h[kk][2 * half + 1] = packsplit(v2, v3, a2l[kk][2 * half + 1]);
            }
        }

        // ============================ layer 2 ============================
        float acc2[16][4];
#pragma unroll
        for (int j = 0; j < 16; ++j) {
            float bv0 = sb2[j * 8 + cb], bv1 = sb2[j * 8 + cb + 1];
            acc2[j][0] = bv0; acc2[j][1] = bv1; acc2[j][2] = bv0; acc2[j][3] = bv1;
        }
#pragma unroll
        for (int kk = 0; kk < 8; ++kk) {
#pragma unroll
            for (int jp = 0; jp < 8; ++jp) {
                unsigned b0, b1, b2, b3;
                ldsm4t(aW2 + (kk * 16 * WS + jp * 16) * 2, b0, b1, b2, b3);
                mma_f16(acc2[2 * jp],     a2h[kk], b0, b1);
                mma_f16(acc2[2 * jp + 1], a2h[kk], b2, b3);
                mma_f16(acc2[2 * jp],     a2l[kk], b0, b1);
                mma_f16(acc2[2 * jp + 1], a2l[kk], b2, b3);
            }
        }
        // relu + repack -> layer-3 A frags
        unsigned a3h[8][4], a3l[8][4];
#pragma unroll
        for (int kk = 0; kk < 8; ++kk) {
#pragma unroll
            for (int half = 0; half < 2; ++half) {
                int j = 2 * kk + half;
                float v0 = fmaxf(acc2[j][0], 0.f), v1 = fmaxf(acc2[j][1], 0.f);
                float v2 = fmaxf(acc2[j][2], 0.f), v3 = fmaxf(acc2[j][3], 0.f);
                a3h[kk][2 * half]     = packsplit(v0, v1, a3l[kk][2 * half]);
                a3h[kk][2 * half + 1] = packsplit(v2, v3, a3l[kk][2 * half + 1]);
            }
        }

        // ============================ layer 3 (N=4 padded to 8) ============================
        float acc3[4];
        acc3[0] = sb3[cb]; acc3[1] = sb3[cb + 1]; acc3[2] = acc3[0]; acc3[3] = acc3[1];
#pragma unroll
        for (int kk = 0; kk < 8; ++kk) {
            unsigned b0, b1;
            ldsm2t(aW3 + (kk * 16 * 8) * 2, b0, b1);
            mma_f16(acc3, a3h[kk], b0, b1);
            mma_f16(acc3, a3l[kk], b0, b1);
        }

        // store ev: cols 0-3 valid (lane%4 < 2)
        if ((lane & 3) < 2) {
            int row = t0 + m0 + (lane >> 2);
            long base = ((long)net * TOK + row) * 4 + cb;
            *(float2*)&g_ev[base] = make_float2(acc3[0], acc3[1]);
            base = ((long)net * TOK + row + 8) * 4 + cb;
            *(float2*)&g_ev[base] = make_float2(acc3[2], acc3[3]);
        }
    }
}

// ---------------------------------------------------------------------------
// Kernel 3: combine nets with splits, volume-render per ray
// ---------------------------------------------------------------------------
__global__ void k_render(float* __restrict__ out) {
    const float* splits = out + BATCH * 3;
    __shared__ float s_scan[P_PTS];
    __shared__ float s_red[P_PTS];
    int b = blockIdx.x;
    int p = threadIdx.x;
    int t = b * P_PTS + p;

    float sp[NNET];
#pragma unroll
    for (int n = 0; n < NNET; ++n) sp[n] = splits[t * NNET + n];

    float ne0 = 0.f, ne1 = 0.f, ne2 = 0.f, ne3 = 0.f;
#pragma unroll
    for (int n = 0; n < NNET; ++n) {
        long base = ((long)n * TOK + t) * 4;
        ne0 = fmaf(g_ev[base + 0], sp[n], ne0);
        ne1 = fmaf(g_ev[base + 1], sp[n], ne1);
        ne2 = fmaf(g_ev[base + 2], sp[n], ne2);
        ne3 = fmaf(g_ev[base + 3], sp[n], ne3);
    }

    float diff = (p < 127) ? g_diffs[p] : 0.f;
    float sd = ne3 * diff;

    s_scan[p] = sd;
    __syncthreads();
#pragma unroll
    for (int off = 1; off < P_PTS; off <<= 1) {
        float v = (p >= off) ? s_scan[p - off] : 0.f;
        __syncthreads();
        s_scan[p] += v;
        __syncthreads();
    }
    float T = expf(s_scan[p]);
    float w = (p < 127) ? T * (1.0f - expf(-sd)) : 0.f;

    float col[3] = {w * ne0, w * ne1, w * ne2};
#pragma unroll
    for (int c = 0; c < 3; ++c) {
        s_red[p] = col[c];
        __syncthreads();
        for (int off = 64; off >= 1; off >>= 1) {
            if (p < off) s_red[p] += s_red[p + off];
            __syncthreads();
        }
        if (p == 0) out[b * 3 + c] = s_red[0];
        __syncthreads();
    }
}

// ---------------------------------------------------------------------------
// Launch
// ---------------------------------------------------------------------------
extern "C" void kernel_launch(void* const* d_in, const int* in_sizes, int n_in,
                              void* d_out, int out_size) {
    const float* ray_o = (const float*)d_in[0];
    const float* ray_d = (const float*)d_in[1];
    const float* s_st  = (const float*)d_in[2];
    const float* s_en  = (const float*)d_in[3];
    // d_in[4] = num_integration_points (hardcoded 128)
    const float* W1 = (const float*)d_in[5];
    const float* b1 = (const float*)d_in[6];
    const float* W2 = (const float*)d_in[7];
    const float* b2 = (const float*)d_in[8];
    const float* W3 = (const float*)d_in[9];
    const float* b3 = (const float*)d_in[10];
    const float* Ws = (const float*)d_in[11];
    const float* bs = (const float*)d_in[12];
    float* out = (float*)d_out;

    cudaFuncSetAttribute(k_mlp, cudaFuncAttributeMaxDynamicSharedMemorySize, SMEM_BYTES);

    k_init<<<1, 128>>>(s_st, s_en);
    k_prep<<<NNET, 256>>>(W1, b1, W2, b2, W3, b3);
    k_features<<<BATCH, 128>>>(ray_o, ray_d, Ws, bs, out + BATCH * 3);
    dim3 grid(GX, NNET);
    k_mlp<<<grid, 256, SMEM_BYTES>>>();
    k_render<<<BATCH, P_PTS>>>(out);
}

// round 13
// speedup vs baseline: 3.9068x; 1.0082x over previous
#include <cuda_runtime.h>
#include <cuda_fp16.h>
#include <math.h>

// ---------------------------------------------------------------------------
// Problem constants
// ---------------------------------------------------------------------------
#define BATCH 1024
#define P_PTS 128
#define TOK   (BATCH * P_PTS)     // 131072 tokens
#define NNET  8
#define HID   128
#define INF   66                   // IN_DIM = 6*10+6
#define KPAD1 80                   // layer-1 K padded to multiple of 16
#define LFREQ 10

// strides (fp16 elems): odd multiples of 8 -> conflict-free ldmatrix
#define XS  88     // X^T rows [128 tok][88]
#define WS  136    // W1/W2 rows [k][136]

#define W1T (KPAD1 * WS)   // 10880 elems
#define W2T (128 * WS)     // 17408
#define W3T (128 * 8)      // 1024
// blob byte offsets (single fp16 weights — no lo terms)
#define B_W1 0
#define B_W2 (B_W1 + W1T * 2)       // 21760
#define B_W3 (B_W2 + W2T * 2)       // 56576
#define BLOB_BYTES (B_W3 + W3T * 2) // 58624

// k_mlp smem layout (bytes)
#define OFF_W   0
#define OFF_B   BLOB_BYTES              // 58624 : b1[128] b2[128] b3[8] floats
#define OFF_X0  (OFF_B + 1056)          // 59680
#define XBUF_BYTES 45056                // hi 22528 + lo 22528
#define OFF_X1  (OFF_X0 + XBUF_BYTES)   // 104736
#define SMEM_BYTES (OFF_X1 + XBUF_BYTES) // 149792

#define GX 128                          // blocks per net
#define TILES_PER_BLOCK (1024 / GX)     // 8

// ---------------------------------------------------------------------------
// Device scratch
// ---------------------------------------------------------------------------
__device__ float g_t[P_PTS];
__device__ float g_diffs[P_PTS - 1];
__device__ __align__(16) __half g_Xhi[TOK * 80];  // [t][80] row-major
__device__ __align__(16) __half g_Xlo[TOK * 80];
__device__ __align__(16) __half g_wblob[NNET][BLOB_BYTES / 2];
__device__ __align__(16) float g_bias[NNET][264];  // b1,b2,b3pad
__device__ float g_ev[NNET * TOK * 4];

// ---------------------------------------------------------------------------
// Accurate sincos (double precision; immune to --use_fast_math rewrites).
// ---------------------------------------------------------------------------
__device__ __forceinline__ void sincos_acc(double x, double* sp, double* cp) {
    int k = __double2int_rn(x * 0.63661977236758138);
    double q = (double)k;
    double r = __fma_rn(q, -1.5707963267948966, x);
    r = __fma_rn(q, -6.123233995736766e-17, r);
    double r2 = r * r;
    double s = __fma_rn(r2, 2.7557319223985893e-06, -1.9841269841269841e-04);
    s = __fma_rn(r2, s, 8.3333333333333332e-03);
    s = __fma_rn(r2, s, -1.6666666666666666e-01);
    s = __fma_rn(r * r2, s, r);
    double c = __fma_rn(r2, -2.7557319223985888e-07, 2.4801587301587302e-05);
    c = __fma_rn(r2, c, -1.3888888888888889e-03);
    c = __fma_rn(r2, c, 4.1666666666666664e-02);
    c = __fma_rn(r2, c, -0.5);
    c = __fma_rn(r2, c, 1.0);
    switch (k & 3) {
        case 0: *sp = s;  *cp = c;  break;
        case 1: *sp = c;  *cp = -s; break;
        case 2: *sp = -s; *cp = -c; break;
        default:*sp = -c; *cp = s;  break;
    }
}

// ---------------------------------------------------------------------------
// Kernel 0: jax partitionable threefry, key (0,42); bits = y0 ^ y1
// ---------------------------------------------------------------------------
__global__ void k_init(const float* __restrict__ sstart,
                       const float* __restrict__ send) {
    __shared__ float st[P_PTS];
    int i = threadIdx.x;
    float start = *sstart, end = *send;
    {
        unsigned x0 = 0u;
        unsigned x1 = (unsigned)i;
        const unsigned ks0 = 0u;
        const unsigned ks1 = 42u;
        const unsigned ks2 = 0x1BD11BDAu ^ 0u ^ 42u;
        x0 += ks0; x1 += ks1;
#define TF_R(r) { x0 += x1; x1 = (x1 << (r)) | (x1 >> (32 - (r))); x1 ^= x0; }
        TF_R(13) TF_R(15) TF_R(26) TF_R(6)
        x0 += ks1; x1 += ks2 + 1u;
        TF_R(17) TF_R(29) TF_R(16) TF_R(24)
        x0 += ks2; x1 += ks0 + 2u;
        TF_R(13) TF_R(15) TF_R(26) TF_R(6)
        x0 += ks0; x1 += ks1 + 3u;
        TF_R(17) TF_R(29) TF_R(16) TF_R(24)
        x0 += ks1; x1 += ks2 + 4u;
        TF_R(13) TF_R(15) TF_R(26) TF_R(6)
        x0 += ks2; x1 += ks0 + 5u;
#undef TF_R
        unsigned bits = x0 ^ x1;
        float u = __uint_as_float((bits >> 9) | 0x3f800000u) - 1.0f;
        float range = __fadd_rn(end, -start);
        float step  = __fdiv_rn(range, 127.0f);
        float basev = __fadd_rn(start, __fmul_rn((float)i, step));
        float tv    = __fadd_rn(basev, __fdiv_rn(__fmul_rn(u, range), 127.0f));
        st[i] = tv;
        g_t[i] = tv;
    }
    __syncthreads();
    if (i < 127) g_diffs[i] = __fadd_rn(st[i + 1], -st[i]);
}

// ---------------------------------------------------------------------------
// Kernel P: weights -> single-fp16 blobs in smem-tile layout (once per net)
// ---------------------------------------------------------------------------
__global__ void k_prep(const float* __restrict__ W1, const float* __restrict__ b1,
                       const float* __restrict__ W2, const float* __restrict__ b2,
                       const float* __restrict__ W3, const float* __restrict__ b3) {
    int net = blockIdx.x;
    int tid = threadIdx.x;
    __half* blob = g_wblob[net];
    const float* W1n = W1 + net * INF * HID;
    const float* W2n = W2 + net * HID * HID;
    const float* W3n = W3 + net * HID * 4;

    for (int idx = tid; idx < W1T; idx += 256) {
        int k = idx / WS, hs = idx % WS;
        float v = (hs < HID && k < INF) ? W1n[k * HID + hs] : 0.f;
        blob[idx] = __float2half_rn(v);
    }
    const int base2 = W1T;
    for (int idx = tid; idx < W2T; idx += 256) {
        int k = idx / WS, hs = idx % WS;
        float v = (hs < HID) ? W2n[k * HID + hs] : 0.f;
        blob[base2 + idx] = __float2half_rn(v);
    }
    const int base3 = W1T + W2T;
    for (int idx = tid; idx < W3T; idx += 256) {
        int k = idx >> 3, o = idx & 7;
        float v = (o < 4) ? W3n[k * 4 + o] : 0.f;
        blob[base3 + idx] = __float2half_rn(v);
    }
    if (tid < 128) {
        g_bias[net][tid]       = b1[net * HID + tid];
        g_bias[net][128 + tid] = b2[net * HID + tid];
    }
    if (tid < 8) g_bias[net][256 + tid] = (tid < 4) ? b3[net * 4 + tid] : 0.f;
}

// ---------------------------------------------------------------------------
// Kernel 1: per-ray block; X written as 2-term fp16 split [t][80] + splits.
// ---------------------------------------------------------------------------
__global__ __launch_bounds__(128)
void k_features(const float* __restrict__ ro,
                const float* __restrict__ rd,
                const float* __restrict__ Ws,
                const float* __restrict__ bsv,
                float* __restrict__ splits_out) {
    __shared__ __half sHi[128 * 80];
    __shared__ __half sLo[128 * 80];
    int tid = threadIdx.x;
    int bray = blockIdx.x;
    int t0 = bray * P_PTS;
    int t = t0 + tid;

    float tp = g_t[tid];
    float o0 = ro[bray * 3 + 0], o1 = ro[bray * 3 + 1], o2 = ro[bray * 3 + 2];
    float d0 = rd[bray * 3 + 0], d1 = rd[bray * 3 + 1], d2 = rd[bray * 3 + 2];
    float r0 = __fadd_rn(__fmul_rn(d0, tp), o0);
    float r1 = __fadd_rn(__fmul_rn(d1, tp), o1);
    float r2 = __fadd_rn(__fmul_rn(d2, tp), o2);

    __half* rowh = &sHi[tid * 80];
    __half* rowl = &sLo[tid * 80];
#define PUT(f, v) { float _v = (v); __half _h = __float2half_rn(_v); \
                    rowh[f] = _h; rowl[f] = __float2half_rn(_v - __half2float(_h)); }
    PUT(0, r0) PUT(1, r1) PUT(2, r2)

    const float pif = 3.14159274101257324f;  // float(np.pi)
    float rc[3] = {r0, r1, r2};
#pragma unroll
    for (int c = 0; c < 3; ++c) {
        double a = (double)__fmul_rn(rc[c], pif);
        double s, co;
        sincos_acc(a, &s, &co);
#pragma unroll
        for (int l = 0; l < LFREQ; ++l) {
            PUT(3 + 6 * l + c,     (float)co)
            PUT(3 + 6 * l + 3 + c, (float)s)
            double sc = s * co;
            double cc = co * co;
            s  = sc + sc;
            co = __fma_rn(2.0, cc, -1.0);
        }
    }
    PUT(63, d0) PUT(64, d1) PUT(65, d2)
#pragma unroll
    for (int f = 66; f < 80; ++f) { rowh[f] = __float2half_rn(0.f); rowl[f] = rowh[f]; }
#undef PUT

    float lg[NNET];
#pragma unroll
    for (int n = 0; n < NNET; ++n)
        lg[n] = bsv[n] + r0 * Ws[0 * NNET + n] + r1 * Ws[1 * NNET + n] + r2 * Ws[2 * NNET + n];
    float mx = lg[0];
#pragma unroll
    for (int n = 1; n < NNET; ++n) mx = fmaxf(mx, lg[n]);
    float sum = 0.f;
    float e[NNET];
#pragma unroll
    for (int n = 0; n < NNET; ++n) { e[n] = expf(lg[n] - mx); sum += e[n]; }
    float inv = __fdiv_rn(1.0f, sum);
#pragma unroll
    for (int n = 0; n < NNET; ++n) splits_out[t * NNET + n] = e[n] * inv;

    __syncthreads();
    const uint4* s4h = (const uint4*)sHi;
    const uint4* s4l = (const uint4*)sLo;
    uint4* g4h = (uint4*)(g_Xhi + (size_t)t0 * 80);
    uint4* g4l = (uint4*)(g_Xlo + (size_t)t0 * 80);
    for (int i = tid; i < 1280; i += 128) {
        g4h[i] = s4h[i];
        g4l[i] = s4l[i];
    }
}

// ---------------------------------------------------------------------------
// Tensor-core MLP: mma.sync m16n8k16 fp16, 2-term activation split, single
// fp16 weights. ILP-scheduled: B-frags preloaded per k-step, all hi-MMAs then
// all lo-MMAs (same-accumulator distance 16); layer 3 uses 4 accumulator sets.
// ---------------------------------------------------------------------------
__device__ __forceinline__ unsigned sptr(const void* p) {
    return (unsigned)__cvta_generic_to_shared(p);
}
__device__ __forceinline__ void cpa16(unsigned dst, const void* src) {
    asm volatile("cp.async.cg.shared.global [%0], [%1], 16;" :: "r"(dst), "l"(src));
}
__device__ __forceinline__ void cpa_commit() { asm volatile("cp.async.commit_group;"); }
__device__ __forceinline__ void cpa_wait0()  { asm volatile("cp.async.wait_group 0;"); }
__device__ __forceinline__ void ldsm4(unsigned a, unsigned& r0, unsigned& r1,
                                      unsigned& r2, unsigned& r3) {
    asm volatile("ldmatrix.sync.aligned.m8n8.x4.shared.b16 {%0,%1,%2,%3}, [%4];"
                 : "=r"(r0), "=r"(r1), "=r"(r2), "=r"(r3) : "r"(a));
}
__device__ __forceinline__ void ldsm4t(unsigned a, unsigned& r0, unsigned& r1,
                                       unsigned& r2, unsigned& r3) {
    asm volatile("ldmatrix.sync.aligned.m8n8.x4.trans.shared.b16 {%0,%1,%2,%3}, [%4];"
                 : "=r"(r0), "=r"(r1), "=r"(r2), "=r"(r3) : "r"(a));
}
__device__ __forceinline__ void ldsm2t(unsigned a, unsigned& r0, unsigned& r1) {
    asm volatile("ldmatrix.sync.aligned.m8n8.x2.trans.shared.b16 {%0,%1}, [%2];"
                 : "=r"(r0), "=r"(r1) : "r"(a));
}
__device__ __forceinline__ void mma_f16(float* d, const unsigned* a, unsigned b0, unsigned b1) {
    asm volatile("mma.sync.aligned.m16n8k16.row.col.f32.f16.f16.f32 "
                 "{%0,%1,%2,%3}, {%4,%5,%6,%7}, {%8,%9}, {%0,%1,%2,%3};"
                 : "+f"(d[0]), "+f"(d[1]), "+f"(d[2]), "+f"(d[3])
                 : "r"(a[0]), "r"(a[1]), "r"(a[2]), "r"(a[3]), "r"(b0), "r"(b1));
}
// split-pack two fp32 into fp16x2 (hi) and residual fp16x2 (lo)
__device__ __forceinline__ unsigned packsplit(float v0, float v1, unsigned& lo) {
    __half h0 = __float2half_rn(v0);
    __half h1 = __float2half_rn(v1);
    __half l0 = __float2half_rn(v0 - __half2float(h0));
    __half l1 = __float2half_rn(v1 - __half2float(h1));
    lo = (unsigned)__half_as_ushort(l0) | ((unsigned)__half_as_ushort(l1) << 16);
    return (unsigned)__half_as_ushort(h0) | ((unsigned)__half_as_ushort(h1) << 16);
}

extern __shared__ char smemc[];

__global__ __launch_bounds__(256, 1)
void k_mlp() {
    const int tid  = threadIdx.x;
    const int lane = tid & 31;
    const int warp = tid >> 5;
    const int net  = blockIdx.y;

    const unsigned sbase = sptr(smemc);
    float* sb1 = (float*)(smemc + OFF_B);
    float* sb2 = (float*)(smemc + OFF_B + 512);
    float* sb3 = (float*)(smemc + OFF_B + 1024);

    // ---- one-time weight + bias blob copy (async) ----
    {
        const char* wsrc = (const char*)g_wblob[net];
        for (int i = tid * 16; i < BLOB_BYTES; i += 256 * 16)
            cpa16(sbase + OFF_W + i, wsrc + i);
        const char* bsrc = (const char*)g_bias[net];
        if (tid * 16 < 1056)
            cpa16(sbase + OFF_B + tid * 16, bsrc + tid * 16);
    }
    // ---- first X tile copy ----
    {
        int t0 = blockIdx.x * 128;
        for (int c = tid; c < 1280; c += 256) {
            int m = c / 10, cc = c - m * 10;
            unsigned d = sbase + OFF_X0 + (m * XS + cc * 8) * 2;
            size_t gsrc = (size_t)(t0 + m) * 80 + cc * 8;
            cpa16(d,         g_Xhi + gsrc);
            cpa16(d + 22528, g_Xlo + gsrc);
        }
    }
    cpa_commit();

    // ---- per-warp fragment geometry ----
    const int m0   = warp * 16;
    const int lrow = lane & 15;
    const int lch  = lane >> 4;
    const int cb   = (lane & 3) * 2;

    const unsigned aW1 = sbase + OFF_W + B_W1 + (lrow * WS + lch * 8) * 2;
    const unsigned aW2 = sbase + OFF_W + B_W2 + (lrow * WS + lch * 8) * 2;
    const unsigned aW3 = sbase + OFF_W + B_W3 + (lrow * 8) * 2;

    for (int it = 0; it < TILES_PER_BLOCK; ++it) {
        const int t0 = (blockIdx.x + GX * it) * 128;
        const unsigned xoff = (it & 1) ? OFF_X1 : OFF_X0;

        cpa_wait0();
        __syncthreads();

        // prefetch next tile into the other buffer
        if (it + 1 < TILES_PER_BLOCK) {
            int tn0 = (blockIdx.x + GX * (it + 1)) * 128;
            unsigned nxoff = ((it + 1) & 1) ? OFF_X1 : OFF_X0;
            for (int c = tid; c < 1280; c += 256) {
                int m = c / 10, cc = c - m * 10;
                unsigned d = sbase + nxoff + (m * XS + cc * 8) * 2;
                size_t gsrc = (size_t)(tn0 + m) * 80 + cc * 8;
                cpa16(d,         g_Xhi + gsrc);
                cpa16(d + 22528, g_Xlo + gsrc);
            }
            cpa_commit();
        }

        const unsigned aXhi = sbase + xoff + ((m0 + lrow) * XS + lch * 8) * 2;
        const unsigned aXlo = aXhi + 22528;

        // ============================ layer 1 ============================
        float acc[16][4];
#pragma unroll
        for (int j = 0; j < 16; ++j) {
            float bv0 = sb1[j * 8 + cb], bv1 = sb1[j * 8 + cb + 1];
            acc[j][0] = bv0; acc[j][1] = bv1; acc[j][2] = bv0; acc[j][3] = bv1;
        }
#pragma unroll
        for (int ks = 0; ks < KPAD1 / 16; ++ks) {
            unsigned ah[4], al[4];
            ldsm4(aXhi + ks * 32, ah[0], ah[1], ah[2], ah[3]);
            ldsm4(aXlo + ks * 32, al[0], al[1], al[2], al[3]);
            unsigned bw[8][4];
#pragma unroll
            for (int jp = 0; jp < 8; ++jp)
                ldsm4t(aW1 + (ks * 16 * WS + jp * 16) * 2,
                       bw[jp][0], bw[jp][1], bw[jp][2], bw[jp][3]);
            // 16 independent hi-MMAs, then 16 lo-MMAs (same-acc distance 16)
#pragma unroll
            for (int jp = 0; jp < 8; ++jp) {
                mma_f16(acc[2 * jp],     ah, bw[jp][0], bw[jp][1]);
                mma_f16(acc[2 * jp + 1], ah, bw[jp][2], bw[jp][3]);
            }
#pragma unroll
            for (int jp = 0; jp < 8; ++jp) {
                mma_f16(acc[2 * jp],     al, bw[jp][0], bw[jp][1]);
                mma_f16(acc[2 * jp + 1], al, bw[jp][2], bw[jp][3]);
            }
        }
        // relu + repack C frags -> layer-2 A frags (registers only)
        unsigned a2h[8][4], a2l[8][4];
#pragma unroll
        for (int kk = 0; kk < 8; ++kk) {
#pragma unroll
            for (int half = 0; half < 2; ++half) {
                int j = 2 * kk + half;
                float v0 = fmaxf(acc[j][0], 0.f), v1 = fmaxf(acc[j][1], 0.f);
                float v2 = fmaxf(acc[j][2], 0.f), v3 = fmaxf(acc[j][3], 0.f);
                a2h[kk][2 * half]     = packsplit(v0, v1, a2l[kk][2 * half]);
                a2h[kk][2 * half + 1] = packsplit(v2, v3, a2l[kk][2 * half + 1]);
            }
        }

        // ============================ layer 2 ============================
        float acc2[16][4];
#pragma unroll
        for (int j = 0; j < 16; ++j) {
            float bv0 = sb2[j * 8 + cb], bv1 = sb2[j * 8 + cb + 1];
            acc2[j][0] = bv0; acc2[j][1] = bv1; acc2[j][2] = bv0; acc2[j][3] = bv1;
        }
#pragma unroll
        for (int kk = 0; kk < 8; ++kk) {
            unsigned bw[8][4];
#pragma unroll
            for (int jp = 0; jp < 8; ++jp)
                ldsm4t(aW2 + (kk * 16 * WS + jp * 16) * 2,
                       bw[jp][0], bw[jp][1], bw[jp][2], bw[jp][3]);
#pragma unroll
            for (int jp = 0; jp < 8; ++jp) {
                mma_f16(acc2[2 * jp],     a2h[kk], bw[jp][0], bw[jp][1]);
                mma_f16(acc2[2 * jp + 1], a2h[kk], bw[jp][2], bw[jp][3]);
            }
#pragma unroll
            for (int jp = 0; jp < 8; ++jp) {
                mma_f16(acc2[2 * jp],     a2l[kk], bw[jp][0], bw[jp][1]);
                mma_f16(acc2[2 * jp + 1], a2l[kk], bw[jp][2], bw[jp][3]);
            }
        }
        // relu + repack -> layer-3 A frags
        unsigned a3h[8][4], a3l[8][4];
#pragma unroll
        for (int kk = 0; kk < 8; ++kk) {
#pragma unroll
            for (int half = 0; half < 2; ++half) {
                int j = 2 * kk + half;
                float v0 = fmaxf(acc2[j][0], 0.f), v1 = fmaxf(acc2[j][1], 0.f);
                float v2 = fmaxf(acc2[j][2], 0.f), v3 = fmaxf(acc2[j][3], 0.f);
                a3h[kk][2 * half]     = packsplit(v0, v1, a3l[kk][2 * half]);
                a3h[kk][2 * half + 1] = packsplit(v2, v3, a3l[kk][2 * half + 1]);
            }
        }

        // ============== layer 3 (N=4 padded to 8, 4 accumulator sets) ==============
        float a3s[4][4];
        a3s[0][0] = sb3[cb]; a3s[0][1] = sb3[cb + 1];
        a3s[0][2] = a3s[0][0]; a3s[0][3] = a3s[0][1];
#pragma unroll
        for (int s = 1; s < 4; ++s) {
            a3s[s][0] = 0.f; a3s[s][1] = 0.f; a3s[s][2] = 0.f; a3s[s][3] = 0.f;
        }
        unsigned b3f[8][2];
#pragma unroll
        for (int kk = 0; kk < 8; ++kk)
            ldsm2t(aW3 + (kk * 16 * 8) * 2, b3f[kk][0], b3f[kk][1]);
#pragma unroll
        for (int kk = 0; kk < 8; ++kk)
            mma_f16(a3s[kk & 3], a3h[kk], b3f[kk][0], b3f[kk][1]);
#pragma unroll
        for (int kk = 0; kk < 8; ++kk)
            mma_f16(a3s[kk & 3], a3l[kk], b3f[kk][0], b3f[kk][1]);
        float acc3[4];
#pragma unroll
        for (int i = 0; i < 4; ++i)
            acc3[i] = (a3s[0][i] + a3s[1][i]) + (a3s[2][i] + a3s[3][i]);

        // store ev: cols 0-3 valid (lane%4 < 2)
        if ((lane & 3) < 2) {
            int row = t0 + m0 + (lane >> 2);
            long base = ((long)net * TOK + row) * 4 + cb;
            *(float2*)&g_ev[base] = make_float2(acc3[0], acc3[1]);
            base = ((long)net * TOK + row + 8) * 4 + cb;
            *(float2*)&g_ev[base] = make_float2(acc3[2], acc3[3]);
        }
    }
}

// ---------------------------------------------------------------------------
// Kernel 3: combine nets with splits, volume-render per ray
// ---------------------------------------------------------------------------
__global__ void k_render(float* __restrict__ out) {
    const float* splits = out + BATCH * 3;
    __shared__ float s_scan[P_PTS];
    __shared__ float s_red[P_PTS];
    int b = blockIdx.x;
    int p = threadIdx.x;
    int t = b * P_PTS + p;

    float sp[NNET];
#pragma unroll
    for (int n = 0; n < NNET; ++n) sp[n] = splits[t * NNET + n];

    float ne0 = 0.f, ne1 = 0.f, ne2 = 0.f, ne3 = 0.f;
#pragma unroll
    for (int n = 0; n < NNET; ++n) {
        long base = ((long)n * TOK + t) * 4;
        ne0 = fmaf(g_ev[base + 0], sp[n], ne0);
        ne1 = fmaf(g_ev[base + 1], sp[n], ne1);
        ne2 = fmaf(g_ev[base + 2], sp[n], ne2);
        ne3 = fmaf(g_ev[base + 3], sp[n], ne3);
    }

    float diff = (p < 127) ? g_diffs[p] : 0.f;
    float sd = ne3 * diff;

    s_scan[p] = sd;
    __syncthreads();
#pragma unroll
    for (int off = 1; off < P_PTS; off <<= 1) {
        float v = (p >= off) ? s_scan[p - off] : 0.f;
        __syncthreads();
        s_scan[p] += v;
        __syncthreads();
    }
    float T = expf(s_scan[p]);
    float w = (p < 127) ? T * (1.0f - expf(-sd)) : 0.f;

    float col[3] = {w * ne0, w * ne1, w * ne2};
#pragma unroll
    for (int c = 0; c < 3; ++c) {
        s_red[p] = col[c];
        __syncthreads();
        for (int off = 64; off >= 1; off >>= 1) {
            if (p < off) s_red[p] += s_red[p + off];
            __syncthreads();
        }
        if (p == 0) out[b * 3 + c] = s_red[0];
        __syncthreads();
    }
}

// ---------------------------------------------------------------------------
// Launch
// ---------------------------------------------------------------------------
extern "C" void kernel_launch(void* const* d_in, const int* in_sizes, int n_in,
                              void* d_out, int out_size) {
    const float* ray_o = (const float*)d_in[0];
    const float* ray_d = (const float*)d_in[1];
    const float* s_st  = (const float*)d_in[2];
    const float* s_en  = (const float*)d_in[3];
    // d_in[4] = num_integration_points (hardcoded 128)
    const float* W1 = (const float*)d_in[5];
    const float* b1 = (const float*)d_in[6];
    const float* W2 = (const float*)d_in[7];
    const float* b2 = (const float*)d_in[8];
    const float* W3 = (const float*)d_in[9];
    const float* b3 = (const float*)d_in[10];
    const float* Ws = (const float*)d_in[11];
    const float* bs = (const float*)d_in[12];
    float* out = (float*)d_out;

    cudaFuncSetAttribute(k_mlp, cudaFuncAttributeMaxDynamicSharedMemorySize, SMEM_BYTES);

    k_init<<<1, 128>>>(s_st, s_en);
    k_prep<<<NNET, 256>>>(W1, b1, W2, b2, W3, b3);
    k_features<<<BATCH, 128>>>(ray_o, ray_d, Ws, bs, out + BATCH * 3);
    dim3 grid(GX, NNET);
    k_mlp<<<grid, 256, SMEM_BYTES>>>();
    k_render<<<BATCH, P_PTS>>>(out);
}

// round 14
// speedup vs baseline: 4.7822x; 1.2241x over previous
#include <cuda_runtime.h>
#include <cuda_fp16.h>
#include <math.h>

// ---------------------------------------------------------------------------
// Problem constants
// ---------------------------------------------------------------------------
#define BATCH 1024
#define P_PTS 128
#define TOK   (BATCH * P_PTS)     // 131072 tokens
#define NNET  8
#define HID   128
#define INF   66                   // IN_DIM = 6*10+6
#define KPAD1 80                   // layer-1 K padded to multiple of 16
#define LFREQ 10

// strides (fp16 elems): odd multiples of 8 -> conflict-free ldmatrix
#define XS  88     // X^T rows [128 tok][88]
#define WS  136    // W1/W2 rows [k][136]

#define W1T (KPAD1 * WS)   // 10880 elems
#define W2T (128 * WS)     // 17408
#define W3T (128 * 8)      // 1024
// blob byte offsets (single fp16 weights — no lo terms)
#define B_W1 0
#define B_W2 (B_W1 + W1T * 2)       // 21760
#define B_W3 (B_W2 + W2T * 2)       // 56576
#define BLOB_BYTES (B_W3 + W3T * 2) // 58624

// k_mlp smem layout (bytes)
#define OFF_W   0
#define OFF_B   BLOB_BYTES              // 58624 : b1[128] b2[128] b3[8] floats
#define OFF_X0  (OFF_B + 1056)          // 59680
#define XBUF_BYTES 45056                // hi 22528 + lo 22528
#define OFF_X1  (OFF_X0 + XBUF_BYTES)   // 104736
#define SMEM_BYTES (OFF_X1 + XBUF_BYTES) // 149792

#define GX 128                          // blocks per net
#define TILES_PER_BLOCK (1024 / GX)     // 8

// ---------------------------------------------------------------------------
// Device scratch
// ---------------------------------------------------------------------------
__device__ float g_t[P_PTS];
__device__ float g_diffs[P_PTS - 1];
__device__ __align__(16) __half g_Xhi[TOK * 80];  // [t][80] row-major
__device__ __align__(16) __half g_Xlo[TOK * 80];
__device__ __align__(16) __half g_wblob[NNET][BLOB_BYTES / 2];
__device__ __align__(16) float g_bias[NNET][264];  // b1,b2,b3pad
__device__ float g_ev[NNET * TOK * 4];

// ---------------------------------------------------------------------------
// Accurate sincos (double precision; immune to --use_fast_math rewrites).
// ---------------------------------------------------------------------------
__device__ __forceinline__ void sincos_acc(double x, double* sp, double* cp) {
    int k = __double2int_rn(x * 0.63661977236758138);
    double q = (double)k;
    double r = __fma_rn(q, -1.5707963267948966, x);
    r = __fma_rn(q, -6.123233995736766e-17, r);
    double r2 = r * r;
    double s = __fma_rn(r2, 2.7557319223985893e-06, -1.9841269841269841e-04);
    s = __fma_rn(r2, s, 8.3333333333333332e-03);
    s = __fma_rn(r2, s, -1.6666666666666666e-01);
    s = __fma_rn(r * r2, s, r);
    double c = __fma_rn(r2, -2.7557319223985888e-07, 2.4801587301587302e-05);
    c = __fma_rn(r2, c, -1.3888888888888889e-03);
    c = __fma_rn(r2, c, 4.1666666666666664e-02);
    c = __fma_rn(r2, c, -0.5);
    c = __fma_rn(r2, c, 1.0);
    switch (k & 3) {
        case 0: *sp = s;  *cp = c;  break;
        case 1: *sp = c;  *cp = -s; break;
        case 2: *sp = -s; *cp = -c; break;
        default:*sp = -c; *cp = s;  break;
    }
}

// ---------------------------------------------------------------------------
// Kernel 0: jax partitionable threefry, key (0,42); bits = y0 ^ y1
// ---------------------------------------------------------------------------
__global__ void k_init(const float* __restrict__ sstart,
                       const float* __restrict__ send) {
    __shared__ float st[P_PTS];
    int i = threadIdx.x;
    float start = *sstart, end = *send;
    {
        unsigned x0 = 0u;
        unsigned x1 = (unsigned)i;
        const unsigned ks0 = 0u;
        const unsigned ks1 = 42u;
        const unsigned ks2 = 0x1BD11BDAu ^ 0u ^ 42u;
        x0 += ks0; x1 += ks1;
#define TF_R(r) { x0 += x1; x1 = (x1 << (r)) | (x1 >> (32 - (r))); x1 ^= x0; }
        TF_R(13) TF_R(15) TF_R(26) TF_R(6)
        x0 += ks1; x1 += ks2 + 1u;
        TF_R(17) TF_R(29) TF_R(16) TF_R(24)
        x0 += ks2; x1 += ks0 + 2u;
        TF_R(13) TF_R(15) TF_R(26) TF_R(6)
        x0 += ks0; x1 += ks1 + 3u;
        TF_R(17) TF_R(29) TF_R(16) TF_R(24)
        x0 += ks1; x1 += ks2 + 4u;
        TF_R(13) TF_R(15) TF_R(26) TF_R(6)
        x0 += ks2; x1 += ks0 + 5u;
#undef TF_R
        unsigned bits = x0 ^ x1;
        float u = __uint_as_float((bits >> 9) | 0x3f800000u) - 1.0f;
        float range = __fadd_rn(end, -start);
        float step  = __fdiv_rn(range, 127.0f);
        float basev = __fadd_rn(start, __fmul_rn((float)i, step));
        float tv    = __fadd_rn(basev, __fdiv_rn(__fmul_rn(u, range), 127.0f));
        st[i] = tv;
        g_t[i] = tv;
    }
    __syncthreads();
    if (i < 127) g_diffs[i] = __fadd_rn(st[i + 1], -st[i]);
}

// ---------------------------------------------------------------------------
// Kernel P: weights -> single-fp16 blobs in smem-tile layout (once per net)
// ---------------------------------------------------------------------------
__global__ void k_prep(const float* __restrict__ W1, const float* __restrict__ b1,
                       const float* __restrict__ W2, const float* __restrict__ b2,
                       const float* __restrict__ W3, const float* __restrict__ b3) {
    int net = blockIdx.x;
    int tid = threadIdx.x;
    __half* blob = g_wblob[net];
    const float* W1n = W1 + net * INF * HID;
    const float* W2n = W2 + net * HID * HID;
    const float* W3n = W3 + net * HID * 4;

    for (int idx = tid; idx < W1T; idx += 256) {
        int k = idx / WS, hs = idx % WS;
        float v = (hs < HID && k < INF) ? W1n[k * HID + hs] : 0.f;
        blob[idx] = __float2half_rn(v);
    }
    const int base2 = W1T;
    for (int idx = tid; idx < W2T; idx += 256) {
        int k = idx / WS, hs = idx % WS;
        float v = (hs < HID) ? W2n[k * HID + hs] : 0.f;
        blob[base2 + idx] = __float2half_rn(v);
    }
    const int base3 = W1T + W2T;
    for (int idx = tid; idx < W3T; idx += 256) {
        int k = idx >> 3, o = idx & 7;
        float v = (o < 4) ? W3n[k * 4 + o] : 0.f;
        blob[base3 + idx] = __float2half_rn(v);
    }
    if (tid < 128) {
        g_bias[net][tid]       = b1[net * HID + tid];
        g_bias[net][128 + tid] = b2[net * HID + tid];
    }
    if (tid < 8) g_bias[net][256 + tid] = (tid < 4) ? b3[net * 4 + tid] : 0.f;
}

// ---------------------------------------------------------------------------
// Kernel 1: per-ray block; X written as 2-term fp16 split [t][80] + splits.
// ---------------------------------------------------------------------------
__global__ __launch_bounds__(128)
void k_features(const float* __restrict__ ro,
                const float* __restrict__ rd,
                const float* __restrict__ Ws,
                const float* __restrict__ bsv,
                float* __restrict__ splits_out) {
    __shared__ __half sHi[128 * 80];
    __shared__ __half sLo[128 * 80];
    int tid = threadIdx.x;
    int bray = blockIdx.x;
    int t0 = bray * P_PTS;
    int t = t0 + tid;

    float tp = g_t[tid];
    float o0 = ro[bray * 3 + 0], o1 = ro[bray * 3 + 1], o2 = ro[bray * 3 + 2];
    float d0 = rd[bray * 3 + 0], d1 = rd[bray * 3 + 1], d2 = rd[bray * 3 + 2];
    float r0 = __fadd_rn(__fmul_rn(d0, tp), o0);
    float r1 = __fadd_rn(__fmul_rn(d1, tp), o1);
    float r2 = __fadd_rn(__fmul_rn(d2, tp), o2);

    __half* rowh = &sHi[tid * 80];
    __half* rowl = &sLo[tid * 80];
#define PUT(f, v) { float _v = (v); __half _h = __float2half_rn(_v); \
                    rowh[f] = _h; rowl[f] = __float2half_rn(_v - __half2float(_h)); }
    PUT(0, r0) PUT(1, r1) PUT(2, r2)

    const float pif = 3.14159274101257324f;  // float(np.pi)
    float rc[3] = {r0, r1, r2};
#pragma unroll
    for (int c = 0; c < 3; ++c) {
        double a = (double)__fmul_rn(rc[c], pif);
        double s, co;
        sincos_acc(a, &s, &co);
#pragma unroll
        for (int l = 0; l < LFREQ; ++l) {
            PUT(3 + 6 * l + c,     (float)co)
            PUT(3 + 6 * l + 3 + c, (float)s)
            double sc = s * co;
            double cc = co * co;
            s  = sc + sc;
            co = __fma_rn(2.0, cc, -1.0);
        }
    }
    PUT(63, d0) PUT(64, d1) PUT(65, d2)
#pragma unroll
    for (int f = 66; f < 80; ++f) { rowh[f] = __float2half_rn(0.f); rowl[f] = rowh[f]; }
#undef PUT

    float lg[NNET];
#pragma unroll
    for (int n = 0; n < NNET; ++n)
        lg[n] = bsv[n] + r0 * Ws[0 * NNET + n] + r1 * Ws[1 * NNET + n] + r2 * Ws[2 * NNET + n];
    float mx = lg[0];
#pragma unroll
    for (int n = 1; n < NNET; ++n) mx = fmaxf(mx, lg[n]);
    float sum = 0.f;
    float e[NNET];
#pragma unroll
    for (int n = 0; n < NNET; ++n) { e[n] = expf(lg[n] - mx); sum += e[n]; }
    float inv = __fdiv_rn(1.0f, sum);
#pragma unroll
    for (int n = 0; n < NNET; ++n) splits_out[t * NNET + n] = e[n] * inv;

    __syncthreads();
    const uint4* s4h = (const uint4*)sHi;
    const uint4* s4l = (const uint4*)sLo;
    uint4* g4h = (uint4*)(g_Xhi + (size_t)t0 * 80);
    uint4* g4l = (uint4*)(g_Xlo + (size_t)t0 * 80);
    for (int i = tid; i < 1280; i += 128) {
        g4h[i] = s4h[i];
        g4l[i] = s4l[i];
    }
}

// ---------------------------------------------------------------------------
// Tensor-core MLP: mma.sync m16n8k16 fp16.
// Layer 1: 2-term act split (X exactness matters). Layer 2: single-fp16 act
// (hi only) — saves 128 of 432 MMAs/tile/warp. Layer 3: 2-term act split.
// Weights single fp16 throughout. Persistent over 8 tiles, cp.async X.
// ---------------------------------------------------------------------------
__device__ __forceinline__ unsigned sptr(const void* p) {
    return (unsigned)__cvta_generic_to_shared(p);
}
__device__ __forceinline__ void cpa16(unsigned dst, const void* src) {
    asm volatile("cp.async.cg.shared.global [%0], [%1], 16;" :: "r"(dst), "l"(src));
}
__device__ __forceinline__ void cpa_commit() { asm volatile("cp.async.commit_group;"); }
__device__ __forceinline__ void cpa_wait0()  { asm volatile("cp.async.wait_group 0;"); }
__device__ __forceinline__ void ldsm4(unsigned a, unsigned& r0, unsigned& r1,
                                      unsigned& r2, unsigned& r3) {
    asm volatile("ldmatrix.sync.aligned.m8n8.x4.shared.b16 {%0,%1,%2,%3}, [%4];"
                 : "=r"(r0), "=r"(r1), "=r"(r2), "=r"(r3) : "r"(a));
}
__device__ __forceinline__ void ldsm4t(unsigned a, unsigned& r0, unsigned& r1,
                                       unsigned& r2, unsigned& r3) {
    asm volatile("ldmatrix.sync.aligned.m8n8.x4.trans.shared.b16 {%0,%1,%2,%3}, [%4];"
                 : "=r"(r0), "=r"(r1), "=r"(r2), "=r"(r3) : "r"(a));
}
__device__ __forceinline__ void ldsm2t(unsigned a, unsigned& r0, unsigned& r1) {
    asm volatile("ldmatrix.sync.aligned.m8n8.x2.trans.shared.b16 {%0,%1}, [%2];"
                 : "=r"(r0), "=r"(r1) : "r"(a));
}
__device__ __forceinline__ void mma_f16(float* d, const unsigned* a, unsigned b0, unsigned b1) {
    asm volatile("mma.sync.aligned.m16n8k16.row.col.f32.f16.f16.f32 "
                 "{%0,%1,%2,%3}, {%4,%5,%6,%7}, {%8,%9}, {%0,%1,%2,%3};"
                 : "+f"(d[0]), "+f"(d[1]), "+f"(d[2]), "+f"(d[3])
                 : "r"(a[0]), "r"(a[1]), "r"(a[2]), "r"(a[3]), "r"(b0), "r"(b1));
}
// split-pack two fp32 into fp16x2 (hi) and residual fp16x2 (lo)
__device__ __forceinline__ unsigned packsplit(float v0, float v1, unsigned& lo) {
    __half h0 = __float2half_rn(v0);
    __half h1 = __float2half_rn(v1);
    __half l0 = __float2half_rn(v0 - __half2float(h0));
    __half l1 = __float2half_rn(v1 - __half2float(h1));
    lo = (unsigned)__half_as_ushort(l0) | ((unsigned)__half_as_ushort(l1) << 16);
    return (unsigned)__half_as_ushort(h0) | ((unsigned)__half_as_ushort(h1) << 16);
}
// plain hi-only pack (v0 -> low half)
__device__ __forceinline__ unsigned packh(float v0, float v1) {
    __half2 h = __floats2half2_rn(v0, v1);
    return *(unsigned*)&h;
}

extern __shared__ char smemc[];

__global__ __launch_bounds__(256, 1)
void k_mlp() {
    const int tid  = threadIdx.x;
    const int lane = tid & 31;
    const int warp = tid >> 5;
    const int net  = blockIdx.y;

    const unsigned sbase = sptr(smemc);
    float* sb1 = (float*)(smemc + OFF_B);
    float* sb2 = (float*)(smemc + OFF_B + 512);
    float* sb3 = (float*)(smemc + OFF_B + 1024);

    // ---- one-time weight + bias blob copy (async) ----
    {
        const char* wsrc = (const char*)g_wblob[net];
        for (int i = tid * 16; i < BLOB_BYTES; i += 256 * 16)
            cpa16(sbase + OFF_W + i, wsrc + i);
        const char* bsrc = (const char*)g_bias[net];
        if (tid * 16 < 1056)
            cpa16(sbase + OFF_B + tid * 16, bsrc + tid * 16);
    }
    // ---- first X tile copy ----
    {
        int t0 = blockIdx.x * 128;
        for (int c = tid; c < 1280; c += 256) {
            int m = c / 10, cc = c - m * 10;
            unsigned d = sbase + OFF_X0 + (m * XS + cc * 8) * 2;
            size_t gsrc = (size_t)(t0 + m) * 80 + cc * 8;
            cpa16(d,         g_Xhi + gsrc);
            cpa16(d + 22528, g_Xlo + gsrc);
        }
    }
    cpa_commit();

    // ---- per-warp fragment geometry ----
    const int m0   = warp * 16;
    const int lrow = lane & 15;
    const int lch  = lane >> 4;
    const int cb   = (lane & 3) * 2;

    const unsigned aW1 = sbase + OFF_W + B_W1 + (lrow * WS + lch * 8) * 2;
    const unsigned aW2 = sbase + OFF_W + B_W2 + (lrow * WS + lch * 8) * 2;
    const unsigned aW3 = sbase + OFF_W + B_W3 + (lrow * 8) * 2;

    for (int it = 0; it < TILES_PER_BLOCK; ++it) {
        const int t0 = (blockIdx.x + GX * it) * 128;
        const unsigned xoff = (it & 1) ? OFF_X1 : OFF_X0;

        cpa_wait0();
        __syncthreads();

        // prefetch next tile into the other buffer
        if (it + 1 < TILES_PER_BLOCK) {
            int tn0 = (blockIdx.x + GX * (it + 1)) * 128;
            unsigned nxoff = ((it + 1) & 1) ? OFF_X1 : OFF_X0;
            for (int c = tid; c < 1280; c += 256) {
                int m = c / 10, cc = c - m * 10;
                unsigned d = sbase + nxoff + (m * XS + cc * 8) * 2;
                size_t gsrc = (size_t)(tn0 + m) * 80 + cc * 8;
                cpa16(d,         g_Xhi + gsrc);
                cpa16(d + 22528, g_Xlo + gsrc);
            }
            cpa_commit();
        }

        const unsigned aXhi = sbase + xoff + ((m0 + lrow) * XS + lch * 8) * 2;
        const unsigned aXlo = aXhi + 22528;

        // ============== layer 1 (2-term act: X hi + X lo, W fp16) ==============
        float acc[16][4];
#pragma unroll
        for (int j = 0; j < 16; ++j) {
            float bv0 = sb1[j * 8 + cb], bv1 = sb1[j * 8 + cb + 1];
            acc[j][0] = bv0; acc[j][1] = bv1; acc[j][2] = bv0; acc[j][3] = bv1;
        }
#pragma unroll
        for (int ks = 0; ks < KPAD1 / 16; ++ks) {
            unsigned ah[4], al[4];
            ldsm4(aXhi + ks * 32, ah[0], ah[1], ah[2], ah[3]);
            ldsm4(aXlo + ks * 32, al[0], al[1], al[2], al[3]);
            unsigned bw[8][4];
#pragma unroll
            for (int jp = 0; jp < 8; ++jp)
                ldsm4t(aW1 + (ks * 16 * WS + jp * 16) * 2,
                       bw[jp][0], bw[jp][1], bw[jp][2], bw[jp][3]);
#pragma unroll
            for (int jp = 0; jp < 8; ++jp) {
                mma_f16(acc[2 * jp],     ah, bw[jp][0], bw[jp][1]);
                mma_f16(acc[2 * jp + 1], ah, bw[jp][2], bw[jp][3]);
            }
#pragma unroll
            for (int jp = 0; jp < 8; ++jp) {
                mma_f16(acc[2 * jp],     al, bw[jp][0], bw[jp][1]);
                mma_f16(acc[2 * jp + 1], al, bw[jp][2], bw[jp][3]);
            }
        }
        // relu + hi-only repack -> layer-2 A frags (single fp16 act)
        unsigned a2h[8][4];
#pragma unroll
        for (int kk = 0; kk < 8; ++kk) {
#pragma unroll
            for (int half = 0; half < 2; ++half) {
                int j = 2 * kk + half;
                float v0 = fmaxf(acc[j][0], 0.f), v1 = fmaxf(acc[j][1], 0.f);
                float v2 = fmaxf(acc[j][2], 0.f), v3 = fmaxf(acc[j][3], 0.f);
                a2h[kk][2 * half]     = packh(v0, v1);
                a2h[kk][2 * half + 1] = packh(v2, v3);
            }
        }

        // ============== layer 2 (single-fp16 act, W fp16) ==============
        float acc2[16][4];
#pragma unroll
        for (int j = 0; j < 16; ++j) {
            float bv0 = sb2[j * 8 + cb], bv1 = sb2[j * 8 + cb + 1];
            acc2[j][0] = bv0; acc2[j][1] = bv1; acc2[j][2] = bv0; acc2[j][3] = bv1;
        }
#pragma unroll
        for (int kk = 0; kk < 8; ++kk) {
            unsigned bw[8][4];
#pragma unroll
            for (int jp = 0; jp < 8; ++jp)
                ldsm4t(aW2 + (kk * 16 * WS + jp * 16) * 2,
                       bw[jp][0], bw[jp][1], bw[jp][2], bw[jp][3]);
#pragma unroll
            for (int jp = 0; jp < 8; ++jp) {
                mma_f16(acc2[2 * jp],     a2h[kk], bw[jp][0], bw[jp][1]);
                mma_f16(acc2[2 * jp + 1], a2h[kk], bw[jp][2], bw[jp][3]);
            }
        }
        // relu + 2-term repack -> layer-3 A frags
        unsigned a3h[8][4], a3l[8][4];
#pragma unroll
        for (int kk = 0; kk < 8; ++kk) {
#pragma unroll
            for (int half = 0; half < 2; ++half) {
                int j = 2 * kk + half;
                float v0 = fmaxf(acc2[j][0], 0.f), v1 = fmaxf(acc2[j][1], 0.f);
                float v2 = fmaxf(acc2[j][2], 0.f), v3 = fmaxf(acc2[j][3], 0.f);
                a3h[kk][2 * half]     = packsplit(v0, v1, a3l[kk][2 * half]);
                a3h[kk][2 * half + 1] = packsplit(v2, v3, a3l[kk][2 * half + 1]);
            }
        }

        // ============== layer 3 (N=4 padded to 8, 4 accumulator sets) ==============
        float a3s[4][4];
        a3s[0][0] = sb3[cb]; a3s[0][1] = sb3[cb + 1];
        a3s[0][2] = a3s[0][0]; a3s[0][3] = a3s[0][1];
#pragma unroll
        for (int s = 1; s < 4; ++s) {
            a3s[s][0] = 0.f; a3s[s][1] = 0.f; a3s[s][2] = 0.f; a3s[s][3] = 0.f;
        }
        unsigned b3f[8][2];
#pragma unroll
        for (int kk = 0; kk < 8; ++kk)
            ldsm2t(aW3 + (kk * 16 * 8) * 2, b3f[kk][0], b3f[kk][1]);
#pragma unroll
        for (int kk = 0; kk < 8; ++kk)
            mma_f16(a3s[kk & 3], a3h[kk], b3f[kk][0], b3f[kk][1]);
#pragma unroll
        for (int kk = 0; kk < 8; ++kk)
            mma_f16(a3s[kk & 3], a3l[kk], b3f[kk][0], b3f[kk][1]);
        float acc3[4];
#pragma unroll
        for (int i = 0; i < 4; ++i)
            acc3[i] = (a3s[0][i] + a3s[1][i]) + (a3s[2][i] + a3s[3][i]);

        // store ev: cols 0-3 valid (lane%4 < 2)
        if ((lane & 3) < 2) {
            int row = t0 + m0 + (lane >> 2);
            long base = ((long)net * TOK + row) * 4 + cb;
            *(float2*)&g_ev[base] = make_float2(acc3[0], acc3[1]);
            base = ((long)net * TOK + row + 8) * 4 + cb;
            *(float2*)&g_ev[base] = make_float2(acc3[2], acc3[3]);
        }
    }
}

// ---------------------------------------------------------------------------
// Kernel 3: combine nets with splits, volume-render per ray
// ---------------------------------------------------------------------------
__global__ void k_render(float* __restrict__ out) {
    const float* splits = out + BATCH * 3;
    __shared__ float s_scan[P_PTS];
    __shared__ float s_red[P_PTS];
    int b = blockIdx.x;
    int p = threadIdx.x;
    int t = b * P_PTS + p;

    float sp[NNET];
#pragma unroll
    for (int n = 0; n < NNET; ++n) sp[n] = splits[t * NNET + n];

    float ne0 = 0.f, ne1 = 0.f, ne2 = 0.f, ne3 = 0.f;
#pragma unroll
    for (int n = 0; n < NNET; ++n) {
        long base = ((long)n * TOK + t) * 4;
        ne0 = fmaf(g_ev[base + 0], sp[n], ne0);
        ne1 = fmaf(g_ev[base + 1], sp[n], ne1);
        ne2 = fmaf(g_ev[base + 2], sp[n], ne2);
        ne3 = fmaf(g_ev[base + 3], sp[n], ne3);
    }

    float diff = (p < 127) ? g_diffs[p] : 0.f;
    float sd = ne3 * diff;

    s_scan[p] = sd;
    __syncthreads();
#pragma unroll
    for (int off = 1; off < P_PTS; off <<= 1) {
        float v = (p >= off) ? s_scan[p - off] : 0.f;
        __syncthreads();
        s_scan[p] += v;
        __syncthreads();
    }
    float T = expf(s_scan[p]);
    float w = (p < 127) ? T * (1.0f - expf(-sd)) : 0.f;

    float col[3] = {w * ne0, w * ne1, w * ne2};
#pragma unroll
    for (int c = 0; c < 3; ++c) {
        s_red[p] = col[c];
        __syncthreads();
        for (int off = 64; off >= 1; off >>= 1) {
            if (p < off) s_red[p] += s_red[p + off];
            __syncthreads();
        }
        if (p == 0) out[b * 3 + c] = s_red[0];
        __syncthreads();
    }
}

// ---------------------------------------------------------------------------
// Launch
// ---------------------------------------------------------------------------
extern "C" void kernel_launch(void* const* d_in, const int* in_sizes, int n_in,
                              void* d_out, int out_size) {
    const float* ray_o = (const float*)d_in[0];
    const float* ray_d = (const float*)d_in[1];
    const float* s_st  = (const float*)d_in[2];
    const float* s_en  = (const float*)d_in[3];
    // d_in[4] = num_integration_points (hardcoded 128)
    const float* W1 = (const float*)d_in[5];
    const float* b1 = (const float*)d_in[6];
    const float* W2 = (const float*)d_in[7];
    const float* b2 = (const float*)d_in[8];
    const float* W3 = (const float*)d_in[9];
    const float* b3 = (const float*)d_in[10];
    const float* Ws = (const float*)d_in[11];
    const float* bs = (const float*)d_in[12];
    float* out = (float*)d_out;

    cudaFuncSetAttribute(k_mlp, cudaFuncAttributeMaxDynamicSharedMemorySize, SMEM_BYTES);

    k_init<<<1, 128>>>(s_st, s_en);
    k_prep<<<NNET, 256>>>(W1, b1, W2, b2, W3, b3);
    k_features<<<BATCH, 128>>>(ray_o, ray_d, Ws, bs, out + BATCH * 3);
    dim3 grid(GX, NNET);
    k_mlp<<<grid, 256, SMEM_BYTES>>>();
    k_render<<<BATCH, P_PTS>>>(out);
}

// round 16
// speedup vs baseline: 7.9462x; 1.6616x over previous
#include <cuda_runtime.h>
#include <cuda_fp16.h>
#include <math.h>

// ---------------------------------------------------------------------------
// Problem constants
// ---------------------------------------------------------------------------
#define BATCH 1024
#define P_PTS 128
#define TOK   (BATCH * P_PTS)     // 131072 tokens
#define NNET  8
#define HID   128
#define INF   66                   // IN_DIM = 6*10+6
#define KPAD1 80                   // layer-1 K padded to multiple of 16
#define LFREQ 10

// strides (fp16 elems): odd multiples of 8 -> conflict-free ldmatrix
#define XS  88     // X^T rows [128 tok][88]
#define WS  136    // W1/W2 rows [k][136]

#define W1T (KPAD1 * WS)   // 10880 elems
#define W2T (128 * WS)     // 17408
#define W3T (128 * 8)      // 1024
// blob byte offsets (single fp16 weights)
#define B_W1 0
#define B_W2 (B_W1 + W1T * 2)       // 21760
#define B_W3 (B_W2 + W2T * 2)       // 56576
#define BLOB_BYTES (B_W3 + W3T * 2) // 58624

// k_mlp smem layout (bytes)
#define OFF_B   BLOB_BYTES              // 58624 : b1[128] b2[128] b3[8] floats
#define OFF_X0  (OFF_B + 1056)          // 59680
#define XBUF_BYTES 22528                // hi only: 128 rows x 88 fp16
#define OFF_X1  (OFF_X0 + XBUF_BYTES)   // 82208
#define SMEM_BYTES (OFF_X1 + XBUF_BYTES) // 104736

#define GX 128                          // blocks per net
#define TILES_PER_BLOCK (1024 / GX)     // 8

// ---------------------------------------------------------------------------
// Device scratch
// ---------------------------------------------------------------------------
__device__ float g_t[P_PTS];
__device__ float g_diffs[P_PTS - 1];
__device__ __align__(16) __half g_Xhi[TOK * 80];  // [t][80] row-major
__device__ __align__(16) __half g_wblob[NNET][BLOB_BYTES / 2];
__device__ __align__(16) float g_bias[NNET][264];  // b1,b2,b3pad
__device__ float g_ev[NNET * TOK * 4];

// ---------------------------------------------------------------------------
// Accurate sincos (double precision; immune to --use_fast_math rewrites).
// ---------------------------------------------------------------------------
__device__ __forceinline__ void sincos_acc(double x, double* sp, double* cp) {
    int k = __double2int_rn(x * 0.63661977236758138);
    double q = (double)k;
    double r = __fma_rn(q, -1.5707963267948966, x);
    r = __fma_rn(q, -6.123233995736766e-17, r);
    double r2 = r * r;
    double s = __fma_rn(r2, 2.7557319223985893e-06, -1.9841269841269841e-04);
    s = __fma_rn(r2, s, 8.3333333333333332e-03);
    s = __fma_rn(r2, s, -1.6666666666666666e-01);
    s = __fma_rn(r * r2, s, r);
    double c = __fma_rn(r2, -2.7557319223985888e-07, 2.4801587301587302e-05);
    c = __fma_rn(r2, c, -1.3888888888888889e-03);
    c = __fma_rn(r2, c, 4.1666666666666664e-02);
    c = __fma_rn(r2, c, -0.5);
    c = __fma_rn(r2, c, 1.0);
    switch (k & 3) {
        case 0: *sp = s;  *cp = c;  break;
        case 1: *sp = c;  *cp = -s; break;
        case 2: *sp = -s; *cp = -c; break;
        default:*sp = -c; *cp = s;  break;
    }
}

// ---------------------------------------------------------------------------
// Kernel 0: jax partitionable threefry, key (0,42); bits = y0 ^ y1
// ---------------------------------------------------------------------------
__global__ void k_init(const float* __restrict__ sstart,
                       const float* __restrict__ send) {
    __shared__ float st[P_PTS];
    int i = threadIdx.x;
    float start = *sstart, end = *send;
    {
        unsigned x0 = 0u;
        unsigned x1 = (unsigned)i;
        const unsigned ks0 = 0u;
        const unsigned ks1 = 42u;
        const unsigned ks2 = 0x1BD11BDAu ^ 0u ^ 42u;
        x0 += ks0; x1 += ks1;
#define TF_R(r) { x0 += x1; x1 = (x1 << (r)) | (x1 >> (32 - (r))); x1 ^= x0; }
        TF_R(13) TF_R(15) TF_R(26) TF_R(6)
        x0 += ks1; x1 += ks2 + 1u;
        TF_R(17) TF_R(29) TF_R(16) TF_R(24)
        x0 += ks2; x1 += ks0 + 2u;
        TF_R(13) TF_R(15) TF_R(26) TF_R(6)
        x0 += ks0; x1 += ks1 + 3u;
        TF_R(17) TF_R(29) TF_R(16) TF_R(24)
        x0 += ks1; x1 += ks2 + 4u;
        TF_R(13) TF_R(15) TF_R(26) TF_R(6)
        x0 += ks2; x1 += ks0 + 5u;
#undef TF_R
        unsigned bits = x0 ^ x1;
        float u = __uint_as_float((bits >> 9) | 0x3f800000u) - 1.0f;
        float range = __fadd_rn(end, -start);
        float step  = __fdiv_rn(range, 127.0f);
        float basev = __fadd_rn(start, __fmul_rn((float)i, step));
        float tv    = __fadd_rn(basev, __fdiv_rn(__fmul_rn(u, range), 127.0f));
        st[i] = tv;
        g_t[i] = tv;
    }
    __syncthreads();
    if (i < 127) g_diffs[i] = __fadd_rn(st[i + 1], -st[i]);
}

// ---------------------------------------------------------------------------
// Kernel P: weights -> single-fp16 blobs in smem-tile layout (once per net)
// ---------------------------------------------------------------------------
__global__ void k_prep(const float* __restrict__ W1, const float* __restrict__ b1,
                       const float* __restrict__ W2, const float* __restrict__ b2,
                       const float* __restrict__ W3, const float* __restrict__ b3) {
    int net = blockIdx.x;
    int tid = threadIdx.x;
    __half* blob = g_wblob[net];
    const float* W1n = W1 + net * INF * HID;
    const float* W2n = W2 + net * HID * HID;
    const float* W3n = W3 + net * HID * 4;

    for (int idx = tid; idx < W1T; idx += 256) {
        int k = idx / WS, hs = idx % WS;
        float v = (hs < HID && k < INF) ? W1n[k * HID + hs] : 0.f;
        blob[idx] = __float2half_rn(v);
    }
    const int base2 = W1T;
    for (int idx = tid; idx < W2T; idx += 256) {
        int k = idx / WS, hs = idx % WS;
        float v = (hs < HID) ? W2n[k * HID + hs] : 0.f;
        blob[base2 + idx] = __float2half_rn(v);
    }
    const int base3 = W1T + W2T;
    for (int idx = tid; idx < W3T; idx += 256) {
        int k = idx >> 3, o = idx & 7;
        float v = (o < 4) ? W3n[k * 4 + o] : 0.f;
        blob[base3 + idx] = __float2half_rn(v);
    }
    if (tid < 128) {
        g_bias[net][tid]       = b1[net * HID + tid];
        g_bias[net][128 + tid] = b2[net * HID + tid];
    }
    if (tid < 8) g_bias[net][256 + tid] = (tid < 4) ? b3[net * 4 + tid] : 0.f;
}

// ---------------------------------------------------------------------------
// Kernel 1: per-ray block; X written as plain fp16 [t][80] + splits.
// ---------------------------------------------------------------------------
__global__ __launch_bounds__(128)
void k_features(const float* __restrict__ ro,
                const float* __restrict__ rd,
                const float* __restrict__ Ws,
                const float* __restrict__ bsv,
                float* __restrict__ splits_out) {
    __shared__ __half sHi[128 * 80];
    int tid = threadIdx.x;
    int bray = blockIdx.x;
    int t0 = bray * P_PTS;
    int t = t0 + tid;

    float tp = g_t[tid];
    float o0 = ro[bray * 3 + 0], o1 = ro[bray * 3 + 1], o2 = ro[bray * 3 + 2];
    float d0 = rd[bray * 3 + 0], d1 = rd[bray * 3 + 1], d2 = rd[bray * 3 + 2];
    float r0 = __fadd_rn(__fmul_rn(d0, tp), o0);
    float r1 = __fadd_rn(__fmul_rn(d1, tp), o1);
    float r2 = __fadd_rn(__fmul_rn(d2, tp), o2);

    __half* rowh = &sHi[tid * 80];
#define PUT(f, v) { rowh[f] = __float2half_rn(v); }
    PUT(0, r0) PUT(1, r1) PUT(2, r2)

    const float pif = 3.14159274101257324f;  // float(np.pi)
    float rc[3] = {r0, r1, r2};
#pragma unroll
    for (int c = 0; c < 3; ++c) {
        double a = (double)__fmul_rn(rc[c], pif);
        double s, co;
        sincos_acc(a, &s, &co);
#pragma unroll
        for (int l = 0; l < LFREQ; ++l) {
            PUT(3 + 6 * l + c,     (float)co)
            PUT(3 + 6 * l + 3 + c, (float)s)
            double sc = s * co;
            double cc = co * co;
            s  = sc + sc;
            co = __fma_rn(2.0, cc, -1.0);
        }
    }
    PUT(63, d0) PUT(64, d1) PUT(65, d2)
#pragma unroll
    for (int f = 66; f < 80; ++f) rowh[f] = __float2half_rn(0.f);
#undef PUT

    float lg[NNET];
#pragma unroll
    for (int n = 0; n < NNET; ++n)
        lg[n] = bsv[n] + r0 * Ws[0 * NNET + n] + r1 * Ws[1 * NNET + n] + r2 * Ws[2 * NNET + n];
    float mx = lg[0];
#pragma unroll
    for (int n = 1; n < NNET; ++n) mx = fmaxf(mx, lg[n]);
    float sum = 0.f;
    float e[NNET];
#pragma unroll
    for (int n = 0; n < NNET; ++n) { e[n] = expf(lg[n] - mx); sum += e[n]; }
    float inv = __fdiv_rn(1.0f, sum);
#pragma unroll
    for (int n = 0; n < NNET; ++n) splits_out[t * NNET + n] = e[n] * inv;

    __syncthreads();
    const uint4* s4h = (const uint4*)sHi;
    uint4* g4h = (uint4*)(g_Xhi + (size_t)t0 * 80);
    for (int i = tid; i < 1280; i += 128)
        g4h[i] = s4h[i];
}

// ---------------------------------------------------------------------------
// Tensor-core MLP: pure fp16 forward (fp32 accumulate), mma.sync m16n8k16.
// 216 MMAs/tile/warp. Persistent over 8 tiles, cp.async double-buffered X.
// ---------------------------------------------------------------------------
__device__ __forceinline__ unsigned sptr(const void* p) {
    return (unsigned)__cvta_generic_to_shared(p);
}
__device__ __forceinline__ void cpa16(unsigned dst, const void* src) {
    asm volatile("cp.async.cg.shared.global [%0], [%1], 16;" :: "r"(dst), "l"(src));
}
__device__ __forceinline__ void cpa_commit() { asm volatile("cp.async.commit_group;"); }
__device__ __forceinline__ void cpa_wait0()  { asm volatile("cp.async.wait_group 0;"); }
__device__ __forceinline__ void ldsm4(unsigned a, unsigned& r0, unsigned& r1,
                                      unsigned& r2, unsigned& r3) {
    asm volatile("ldmatrix.sync.aligned.m8n8.x4.shared.b16 {%0,%1,%2,%3}, [%4];"
                 : "=r"(r0), "=r"(r1), "=r"(r2), "=r"(r3) : "r"(a));
}
__device__ __forceinline__ void ldsm4t(unsigned a, unsigned& r0, unsigned& r1,
                                       unsigned& r2, unsigned& r3) {
    asm volatile("ldmatrix.sync.aligned.m8n8.x4.trans.shared.b16 {%0,%1,%2,%3}, [%4];"
                 : "=r"(r0), "=r"(r1), "=r"(r2), "=r"(r3) : "r"(a));
}
__device__ __forceinline__ void ldsm2t(unsigned a, unsigned& r0, unsigned& r1) {
    asm volatile("ldmatrix.sync.aligned.m8n8.x2.trans.shared.b16 {%0,%1}, [%2];"
                 : "=r"(r0), "=r"(r1) : "r"(a));
}
__device__ __forceinline__ void mma_f16(float* d, const unsigned* a, unsigned b0, unsigned b1) {
    asm volatile("mma.sync.aligned.m16n8k16.row.col.f32.f16.f16.f32 "
                 "{%0,%1,%2,%3}, {%4,%5,%6,%7}, {%8,%9}, {%0,%1,%2,%3};"
                 : "+f"(d[0]), "+f"(d[1]), "+f"(d[2]), "+f"(d[3])
                 : "r"(a[0]), "r"(a[1]), "r"(a[2]), "r"(a[3]), "r"(b0), "r"(b1));
}
// plain fp16x2 pack (v0 -> low half)
__device__ __forceinline__ unsigned packh(float v0, float v1) {
    __half2 h = __floats2half2_rn(v0, v1);
    return *(unsigned*)&h;
}

extern __shared__ char smemc[];

__global__ __launch_bounds__(256, 1)
void k_mlp() {
    const int tid  = threadIdx.x;
    const int lane = tid & 31;
    const int warp = tid >> 5;
    const int net  = blockIdx.y;

    const unsigned sbase = sptr(smemc);
    float* sb1 = (float*)(smemc + OFF_B);
    float* sb2 = (float*)(smemc + OFF_B + 512);
    float* sb3 = (float*)(smemc + OFF_B + 1024);

    // ---- one-time weight + bias blob copy (async) ----
    {
        const char* wsrc = (const char*)g_wblob[net];
        for (int i = tid * 16; i < BLOB_BYTES; i += 256 * 16)
            cpa16(sbase + i, wsrc + i);
        const char* bsrc = (const char*)g_bias[net];
        if (tid * 16 < 1056)
            cpa16(sbase + OFF_B + tid * 16, bsrc + tid * 16);
    }
    // ---- first X tile copy ----
    {
        int t0 = blockIdx.x * 128;
        for (int c = tid; c < 640; c += 256) {
            int m = c / 5, cc = c - m * 5;     // 5 x 16B chunks cover 80 fp16
            unsigned d = sbase + OFF_X0 + (m * XS + cc * 16) * 2;
            size_t gsrc = (size_t)(t0 + m) * 80 + cc * 16;
            cpa16(d,     g_Xhi + gsrc);
            cpa16(d + 16, g_Xhi + gsrc + 8);
        }
    }
    cpa_commit();

    // ---- per-warp fragment geometry ----
    const int m0   = warp * 16;
    const int lrow = lane & 15;
    const int lch  = lane >> 4;
    const int cb   = (lane & 3) * 2;

    const unsigned aW1 = sbase + B_W1 + (lrow * WS + lch * 8) * 2;
    const unsigned aW2 = sbase + B_W2 + (lrow * WS + lch * 8) * 2;
    const unsigned aW3 = sbase + B_W3 + (lrow * 8) * 2;

    for (int it = 0; it < TILES_PER_BLOCK; ++it) {
        const int t0 = (blockIdx.x + GX * it) * 128;
        const unsigned xoff = (it & 1) ? OFF_X1 : OFF_X0;

        cpa_wait0();
        __syncthreads();

        // prefetch next tile into the other buffer
        if (it + 1 < TILES_PER_BLOCK) {
            int tn0 = (blockIdx.x + GX * (it + 1)) * 128;
            unsigned nxoff = ((it + 1) & 1) ? OFF_X1 : OFF_X0;
            for (int c = tid; c < 640; c += 256) {
                int m = c / 5, cc = c - m * 5;
                unsigned d = sbase + nxoff + (m * XS + cc * 16) * 2;
                size_t gsrc = (size_t)(tn0 + m) * 80 + cc * 16;
                cpa16(d,     g_Xhi + gsrc);
                cpa16(d + 16, g_Xhi + gsrc + 8);
            }
            cpa_commit();
        }

        const unsigned aXhi = sbase + xoff + ((m0 + lrow) * XS + lch * 8) * 2;

        // ============== layer 1 (fp16 act, fp16 W) ==============
        float acc[16][4];
#pragma unroll
        for (int j = 0; j < 16; ++j) {
            float bv0 = sb1[j * 8 + cb], bv1 = sb1[j * 8 + cb + 1];
            acc[j][0] = bv0; acc[j][1] = bv1; acc[j][2] = bv0; acc[j][3] = bv1;
        }
#pragma unroll
        for (int ks = 0; ks < KPAD1 / 16; ++ks) {
            unsigned ah[4];
            ldsm4(aXhi + ks * 32, ah[0], ah[1], ah[2], ah[3]);
            unsigned bw[8][4];
#pragma unroll
            for (int jp = 0; jp < 8; ++jp)
                ldsm4t(aW1 + (ks * 16 * WS + jp * 16) * 2,
                       bw[jp][0], bw[jp][1], bw[jp][2], bw[jp][3]);
#pragma unroll
            for (int jp = 0; jp < 8; ++jp) {
                mma_f16(acc[2 * jp],     ah, bw[jp][0], bw[jp][1]);
                mma_f16(acc[2 * jp + 1], ah, bw[jp][2], bw[jp][3]);
            }
        }
        // relu + pack -> layer-2 A frags
        unsigned a2h[8][4];
#pragma unroll
        for (int kk = 0; kk < 8; ++kk) {
#pragma unroll
            for (int half = 0; half < 2; ++half) {
                int j = 2 * kk + half;
                a2h[kk][2 * half]     = packh(fmaxf(acc[j][0], 0.f), fmaxf(acc[j][1], 0.f));
                a2h[kk][2 * half + 1] = packh(fmaxf(acc[j][2], 0.f), fmaxf(acc[j][3], 0.f));
            }
        }

        // ============== layer 2 (fp16 act, fp16 W) ==============
        float acc2[16][4];
#pragma unroll
        for (int j = 0; j < 16; ++j) {
            float bv0 = sb2[j * 8 + cb], bv1 = sb2[j * 8 + cb + 1];
            acc2[j][0] = bv0; acc2[j][1] = bv1; acc2[j][2] = bv0; acc2[j][3] = bv1;
        }
#pragma unroll
        for (int kk = 0; kk < 8; ++kk) {
            unsigned bw[8][4];
#pragma unroll
            for (int jp = 0; jp < 8; ++jp)
                ldsm4t(aW2 + (kk * 16 * WS + jp * 16) * 2,
                       bw[jp][0], bw[jp][1], bw[jp][2], bw[jp][3]);
#pragma unroll
            for (int jp = 0; jp < 8; ++jp) {
                mma_f16(acc2[2 * jp],     a2h[kk], bw[jp][0], bw[jp][1]);
                mma_f16(acc2[2 * jp + 1], a2h[kk], bw[jp][2], bw[jp][3]);
            }
        }
        // relu + pack -> layer-3 A frags
        unsigned a3h[8][4];
#pragma unroll
        for (int kk = 0; kk < 8; ++kk) {
#pragma unroll
            for (int half = 0; half < 2; ++half) {
                int j = 2 * kk + half;
                a3h[kk][2 * half]     = packh(fmaxf(acc2[j][0], 0.f), fmaxf(acc2[j][1], 0.f));
                a3h[kk][2 * half + 1] = packh(fmaxf(acc2[j][2], 0.f), fmaxf(acc2[j][3], 0.f));
            }
        }

        // ============== layer 3 (N=4 padded to 8, 4 accumulator sets) ==============
        float a3s[4][4];
        a3s[0][0] = sb3[cb]; a3s[0][1] = sb3[cb + 1];
        a3s[0][2] = a3s[0][0]; a3s[0][3] = a3s[0][1];
#pragma unroll
        for (int s = 1; s < 4; ++s) {
            a3s[s][0] = 0.f; a3s[s][1] = 0.f; a3s[s][2] = 0.f; a3s[s][3] = 0.f;
        }
        unsigned b3f[8][2];
#pragma unroll
        for (int kk = 0; kk < 8; ++kk)
            ldsm2t(aW3 + (kk * 16 * 8) * 2, b3f[kk][0], b3f[kk][1]);
#pragma unroll
        for (int kk = 0; kk < 8; ++kk)
            mma_f16(a3s[kk & 3], a3h[kk], b3f[kk][0], b3f[kk][1]);
        float acc3[4];
#pragma unroll
        for (int i = 0; i < 4; ++i)
            acc3[i] = (a3s[0][i] + a3s[1][i]) + (a3s[2][i] + a3s[3][i]);

        // store ev: cols 0-3 valid (lane%4 < 2)
        if ((lane & 3) < 2) {
            int row = t0 + m0 + (lane >> 2);
            long base = ((long)net * TOK + row) * 4 + cb;
            *(float2*)&g_ev[base] = make_float2(acc3[0], acc3[1]);
            base = ((long)net * TOK + row + 8) * 4 + cb;
            *(float2*)&g_ev[base] = make_float2(acc3[2], acc3[3]);
        }
    }
}

// ---------------------------------------------------------------------------
// Kernel 3: combine nets with splits, volume-render per ray
// ---------------------------------------------------------------------------
__global__ void k_render(float* __restrict__ out) {
    const float* splits = out + BATCH * 3;
    __shared__ float s_scan[P_PTS];
    __shared__ float s_red[P_PTS];
    int b = blockIdx.x;
    int p = threadIdx.x;
    int t = b * P_PTS + p;

    float sp[NNET];
#pragma unroll
    for (int n = 0; n < NNET; ++n) sp[n] = splits[t * NNET + n];

    float ne0 = 0.f, ne1 = 0.f, ne2 = 0.f, ne3 = 0.f;
#pragma unroll
    for (int n = 0; n < NNET; ++n) {
        long base = ((long)n * TOK + t) * 4;
        ne0 = fmaf(g_ev[base + 0], sp[n], ne0);
        ne1 = fmaf(g_ev[base + 1], sp[n], ne1);
        ne2 = fmaf(g_ev[base + 2], sp[n], ne2);
        ne3 = fmaf(g_ev[base + 3], sp[n], ne3);
    }

    float diff = (p < 127) ? g_diffs[p] : 0.f;
    float sd = ne3 * diff;

    s_scan[p] = sd;
    __syncthreads();
#pragma unroll
    for (int off = 1; off < P_PTS; off <<= 1) {
        float v = (p >= off) ? s_scan[p - off] : 0.f;
        __syncthreads();
        s_scan[p] += v;
        __syncthreads();
    }
    float T = expf(s_scan[p]);
    float w = (p < 127) ? T * (1.0f - expf(-sd)) : 0.f;

    float col[3] = {w * ne0, w * ne1, w * ne2};
#pragma unroll
    for (int c = 0; c < 3; ++c) {
        s_red[p] = col[c];
        __syncthreads();
        for (int off = 64; off >= 1; off >>= 1) {
            if (p < off) s_red[p] += s_red[p + off];
            __syncthreads();
        }
        if (p == 0) out[b * 3 + c] = s_red[0];
        __syncthreads();
    }
}

// ---------------------------------------------------------------------------
// Launch
// ---------------------------------------------------------------------------
extern "C" void kernel_launch(void* const* d_in, const int* in_sizes, int n_in,
                              void* d_out, int out_size) {
    const float* ray_o = (const float*)d_in[0];
    const float* ray_d = (const float*)d_in[1];
    const float* s_st  = (const float*)d_in[2];
    const float* s_en  = (const float*)d_in[3];
    // d_in[4] = num_integration_points (hardcoded 128)
    const float* W1 = (const float*)d_in[5];
    const float* b1 = (const float*)d_in[6];
    const float* W2 = (const float*)d_in[7];
    const float* b2 = (const float*)d_in[8];
    const float* W3 = (const float*)d_in[9];
    const float* b3 = (const float*)d_in[10];
    const float* Ws = (const float*)d_in[11];
    const float* bs = (const float*)d_in[12];
    float* out = (float*)d_out;

    cudaFuncSetAttribute(k_mlp, cudaFuncAttributeMaxDynamicSharedMemorySize, SMEM_BYTES);

    k_init<<<1, 128>>>(s_st, s_en);
    k_prep<<<NNET, 256>>>(W1, b1, W2, b2, W3, b3);
    k_features<<<BATCH, 128>>>(ray_o, ray_d, Ws, bs, out + BATCH * 3);
    dim3 grid(GX, NNET);
    k_mlp<<<grid, 256, SMEM_BYTES>>>();
    k_render<<<BATCH, P_PTS>>>(out);
}

// round 17
// speedup vs baseline: 8.5511x; 1.0761x over previous
#include <cuda_runtime.h>
#include <cuda_fp16.h>
#include <math.h>

// ---------------------------------------------------------------------------
// Problem constants
// ---------------------------------------------------------------------------
#define BATCH 1024
#define P_PTS 128
#define TOK   (BATCH * P_PTS)     // 131072 tokens
#define NNET  8
#define HID   128
#define INF   66                   // IN_DIM = 6*10+6
#define KPAD1 80                   // layer-1 K padded to multiple of 16
#define LFREQ 10

// strides (fp16 elems): odd multiples of 8 -> conflict-free ldmatrix
#define XS  88     // X^T rows [128 tok][88]
#define WS  136    // W1/W2 rows [k][136]

#define W1T (KPAD1 * WS)   // 10880 elems
#define W2T (128 * WS)     // 17408
#define W3T (128 * 8)      // 1024
// blob byte offsets (single fp16 weights)
#define B_W1 0
#define B_W2 (B_W1 + W1T * 2)       // 21760
#define B_W3 (B_W2 + W2T * 2)       // 56576
#define BLOB_BYTES (B_W3 + W3T * 2) // 58624

// k_mlp smem layout (bytes)
#define OFF_B   BLOB_BYTES              // 58624 : b1[128] b2[128] b3[8] floats
#define OFF_X0  (OFF_B + 1056)          // 59680
#define XBUF_BYTES 22528                // 128 rows x 88 fp16
#define OFF_X1  (OFF_X0 + XBUF_BYTES)   // 82208
#define SMEM_BYTES (OFF_X1 + XBUF_BYTES) // 104736

#define GX 128                          // blocks per net
#define TILES_PER_BLOCK (1024 / GX)     // 8

// ---------------------------------------------------------------------------
// Device scratch
// ---------------------------------------------------------------------------
__device__ float g_t[P_PTS];
__device__ float g_diffs[P_PTS - 1];
__device__ __align__(16) __half g_Xhi[TOK * 80];  // [t][80] row-major
__device__ __align__(16) __half g_wblob[NNET][BLOB_BYTES / 2];
__device__ __align__(16) float g_bias[NNET][264];  // b1,b2,b3pad
__device__ float g_ev[NNET * TOK * 4];

// ---------------------------------------------------------------------------
// Accurate sincos (double precision; immune to --use_fast_math rewrites).
// ---------------------------------------------------------------------------
__device__ __forceinline__ void sincos_acc(double x, double* sp, double* cp) {
    int k = __double2int_rn(x * 0.63661977236758138);
    double q = (double)k;
    double r = __fma_rn(q, -1.5707963267948966, x);
    r = __fma_rn(q, -6.123233995736766e-17, r);
    double r2 = r * r;
    double s = __fma_rn(r2, 2.7557319223985893e-06, -1.9841269841269841e-04);
    s = __fma_rn(r2, s, 8.3333333333333332e-03);
    s = __fma_rn(r2, s, -1.6666666666666666e-01);
    s = __fma_rn(r * r2, s, r);
    double c = __fma_rn(r2, -2.7557319223985888e-07, 2.4801587301587302e-05);
    c = __fma_rn(r2, c, -1.3888888888888889e-03);
    c = __fma_rn(r2, c, 4.1666666666666664e-02);
    c = __fma_rn(r2, c, -0.5);
    c = __fma_rn(r2, c, 1.0);
    switch (k & 3) {
        case 0: *sp = s;  *cp = c;  break;
        case 1: *sp = c;  *cp = -s; break;
        case 2: *sp = -s; *cp = -c; break;
        default:*sp = -c; *cp = s;  break;
    }
}

// ---------------------------------------------------------------------------
// Kernel 0: jax partitionable threefry, key (0,42); bits = y0 ^ y1
// ---------------------------------------------------------------------------
__global__ void k_init(const float* __restrict__ sstart,
                       const float* __restrict__ send) {
    __shared__ float st[P_PTS];
    int i = threadIdx.x;
    float start = *sstart, end = *send;
    {
        unsigned x0 = 0u;
        unsigned x1 = (unsigned)i;
        const unsigned ks0 = 0u;
        const unsigned ks1 = 42u;
        const unsigned ks2 = 0x1BD11BDAu ^ 0u ^ 42u;
        x0 += ks0; x1 += ks1;
#define TF_R(r) { x0 += x1; x1 = (x1 << (r)) | (x1 >> (32 - (r))); x1 ^= x0; }
        TF_R(13) TF_R(15) TF_R(26) TF_R(6)
        x0 += ks1; x1 += ks2 + 1u;
        TF_R(17) TF_R(29) TF_R(16) TF_R(24)
        x0 += ks2; x1 += ks0 + 2u;
        TF_R(13) TF_R(15) TF_R(26) TF_R(6)
        x0 += ks0; x1 += ks1 + 3u;
        TF_R(17) TF_R(29) TF_R(16) TF_R(24)
        x0 += ks1; x1 += ks2 + 4u;
        TF_R(13) TF_R(15) TF_R(26) TF_R(6)
        x0 += ks2; x1 += ks0 + 5u;
#undef TF_R
        unsigned bits = x0 ^ x1;
        float u = __uint_as_float((bits >> 9) | 0x3f800000u) - 1.0f;
        float range = __fadd_rn(end, -start);
        float step  = __fdiv_rn(range, 127.0f);
        float basev = __fadd_rn(start, __fmul_rn((float)i, step));
        float tv    = __fadd_rn(basev, __fdiv_rn(__fmul_rn(u, range), 127.0f));
        st[i] = tv;
        g_t[i] = tv;
    }
    __syncthreads();
    if (i < 127) g_diffs[i] = __fadd_rn(st[i + 1], -st[i]);
}

// ---------------------------------------------------------------------------
// Kernel P: weights -> single-fp16 blobs in smem-tile layout (once per net)
// ---------------------------------------------------------------------------
__global__ void k_prep(const float* __restrict__ W1, const float* __restrict__ b1,
                       const float* __restrict__ W2, const float* __restrict__ b2,
                       const float* __restrict__ W3, const float* __restrict__ b3) {
    int net = blockIdx.x;
    int tid = threadIdx.x;
    __half* blob = g_wblob[net];
    const float* W1n = W1 + net * INF * HID;
    const float* W2n = W2 + net * HID * HID;
    const float* W3n = W3 + net * HID * 4;

    for (int idx = tid; idx < W1T; idx += 256) {
        int k = idx / WS, hs = idx % WS;
        float v = (hs < HID && k < INF) ? W1n[k * HID + hs] : 0.f;
        blob[idx] = __float2half_rn(v);
    }
    const int base2 = W1T;
    for (int idx = tid; idx < W2T; idx += 256) {
        int k = idx / WS, hs = idx % WS;
        float v = (hs < HID) ? W2n[k * HID + hs] : 0.f;
        blob[base2 + idx] = __float2half_rn(v);
    }
    const int base3 = W1T + W2T;
    for (int idx = tid; idx < W3T; idx += 256) {
        int k = idx >> 3, o = idx & 7;
        float v = (o < 4) ? W3n[k * 4 + o] : 0.f;
        blob[base3 + idx] = __float2half_rn(v);
    }
    if (tid < 128) {
        g_bias[net][tid]       = b1[net * HID + tid];
        g_bias[net][128 + tid] = b2[net * HID + tid];
    }
    if (tid < 8) g_bias[net][256 + tid] = (tid < 4) ? b3[net * 4 + tid] : 0.f;
}

// ---------------------------------------------------------------------------
// Kernel 1: per-ray block; X written as plain fp16 [t][80] + splits.
// ---------------------------------------------------------------------------
__global__ __launch_bounds__(128)
void k_features(const float* __restrict__ ro,
                const float* __restrict__ rd,
                const float* __restrict__ Ws,
                const float* __restrict__ bsv,
                float* __restrict__ splits_out) {
    __shared__ __half sHi[128 * 80];
    int tid = threadIdx.x;
    int bray = blockIdx.x;
    int t0 = bray * P_PTS;
    int t = t0 + tid;

    float tp = g_t[tid];
    float o0 = ro[bray * 3 + 0], o1 = ro[bray * 3 + 1], o2 = ro[bray * 3 + 2];
    float d0 = rd[bray * 3 + 0], d1 = rd[bray * 3 + 1], d2 = rd[bray * 3 + 2];
    float r0 = __fadd_rn(__fmul_rn(d0, tp), o0);
    float r1 = __fadd_rn(__fmul_rn(d1, tp), o1);
    float r2 = __fadd_rn(__fmul_rn(d2, tp), o2);

    __half* rowh = &sHi[tid * 80];
#define PUT(f, v) { rowh[f] = __float2half_rn(v); }
    PUT(0, r0) PUT(1, r1) PUT(2, r2)

    const float pif = 3.14159274101257324f;  // float(np.pi)
    float rc[3] = {r0, r1, r2};
#pragma unroll
    for (int c = 0; c < 3; ++c) {
        double a = (double)__fmul_rn(rc[c], pif);
        double s, co;
        sincos_acc(a, &s, &co);
#pragma unroll
        for (int l = 0; l < LFREQ; ++l) {
            PUT(3 + 6 * l + c,     (float)co)
            PUT(3 + 6 * l + 3 + c, (float)s)
            double sc = s * co;
            double cc = co * co;
            s  = sc + sc;
            co = __fma_rn(2.0, cc, -1.0);
        }
    }
    PUT(63, d0) PUT(64, d1) PUT(65, d2)
#pragma unroll
    for (int f = 66; f < 80; ++f) rowh[f] = __float2half_rn(0.f);
#undef PUT

    float lg[NNET];
#pragma unroll
    for (int n = 0; n < NNET; ++n)
        lg[n] = bsv[n] + r0 * Ws[0 * NNET + n] + r1 * Ws[1 * NNET + n] + r2 * Ws[2 * NNET + n];
    float mx = lg[0];
#pragma unroll
    for (int n = 1; n < NNET; ++n) mx = fmaxf(mx, lg[n]);
    float sum = 0.f;
    float e[NNET];
#pragma unroll
    for (int n = 0; n < NNET; ++n) { e[n] = expf(lg[n] - mx); sum += e[n]; }
    float inv = __fdiv_rn(1.0f, sum);
#pragma unroll
    for (int n = 0; n < NNET; ++n) splits_out[t * NNET + n] = e[n] * inv;

    __syncthreads();
    const uint4* s4h = (const uint4*)sHi;
    uint4* g4h = (uint4*)(g_Xhi + (size_t)t0 * 80);
    for (int i = tid; i < 1280; i += 128)
        g4h[i] = s4h[i];
}

// ---------------------------------------------------------------------------
// Tensor-core MLP: pure fp16 forward (fp32 accumulate), mma.sync m16n8k16.
// 4 warps/block, M=32 tokens/warp (two 16-row halves) -> weight-fragment smem
// traffic per MAC halves vs 16-token warps. Persistent over 8 tiles.
// ---------------------------------------------------------------------------
__device__ __forceinline__ unsigned sptr(const void* p) {
    return (unsigned)__cvta_generic_to_shared(p);
}
__device__ __forceinline__ void cpa16(unsigned dst, const void* src) {
    asm volatile("cp.async.cg.shared.global [%0], [%1], 16;" :: "r"(dst), "l"(src));
}
__device__ __forceinline__ void cpa_commit() { asm volatile("cp.async.commit_group;"); }
__device__ __forceinline__ void cpa_wait0()  { asm volatile("cp.async.wait_group 0;"); }
__device__ __forceinline__ void ldsm4(unsigned a, unsigned& r0, unsigned& r1,
                                      unsigned& r2, unsigned& r3) {
    asm volatile("ldmatrix.sync.aligned.m8n8.x4.shared.b16 {%0,%1,%2,%3}, [%4];"
                 : "=r"(r0), "=r"(r1), "=r"(r2), "=r"(r3) : "r"(a));
}
__device__ __forceinline__ void ldsm4t(unsigned a, unsigned& r0, unsigned& r1,
                                       unsigned& r2, unsigned& r3) {
    asm volatile("ldmatrix.sync.aligned.m8n8.x4.trans.shared.b16 {%0,%1,%2,%3}, [%4];"
                 : "=r"(r0), "=r"(r1), "=r"(r2), "=r"(r3) : "r"(a));
}
__device__ __forceinline__ void ldsm2t(unsigned a, unsigned& r0, unsigned& r1) {
    asm volatile("ldmatrix.sync.aligned.m8n8.x2.trans.shared.b16 {%0,%1}, [%2];"
                 : "=r"(r0), "=r"(r1) : "r"(a));
}
__device__ __forceinline__ void mma_f16(float* d, const unsigned* a, unsigned b0, unsigned b1) {
    asm volatile("mma.sync.aligned.m16n8k16.row.col.f32.f16.f16.f32 "
                 "{%0,%1,%2,%3}, {%4,%5,%6,%7}, {%8,%9}, {%0,%1,%2,%3};"
                 : "+f"(d[0]), "+f"(d[1]), "+f"(d[2]), "+f"(d[3])
                 : "r"(a[0]), "r"(a[1]), "r"(a[2]), "r"(a[3]), "r"(b0), "r"(b1));
}
// plain fp16x2 pack (v0 -> low half)
__device__ __forceinline__ unsigned packh(float v0, float v1) {
    __half2 h = __floats2half2_rn(v0, v1);
    return *(unsigned*)&h;
}

extern __shared__ char smemc[];

__global__ __launch_bounds__(128)
void k_mlp() {
    const int tid  = threadIdx.x;
    const int lane = tid & 31;
    const int warp = tid >> 5;   // 0..3
    const int net  = blockIdx.y;

    const unsigned sbase = sptr(smemc);
    float* sb1 = (float*)(smemc + OFF_B);
    float* sb2 = (float*)(smemc + OFF_B + 512);
    float* sb3 = (float*)(smemc + OFF_B + 1024);

    // ---- one-time weight + bias blob copy (async) ----
    {
        const char* wsrc = (const char*)g_wblob[net];
        for (int i = tid * 16; i < BLOB_BYTES; i += 128 * 16)
            cpa16(sbase + i, wsrc + i);
        const char* bsrc = (const char*)g_bias[net];
        if (tid * 16 < 1056)
            cpa16(sbase + OFF_B + tid * 16, bsrc + tid * 16);
    }
    // ---- first X tile copy ----
    {
        int t0 = blockIdx.x * 128;
        for (int c = tid; c < 640; c += 128) {
            int m = c / 5, cc = c - m * 5;     // 5 x 16B chunks cover 80 fp16
            unsigned d = sbase + OFF_X0 + (m * XS + cc * 16) * 2;
            size_t gsrc = (size_t)(t0 + m) * 80 + cc * 16;
            cpa16(d,     g_Xhi + gsrc);
            cpa16(d + 16, g_Xhi + gsrc + 8);
        }
    }
    cpa_commit();

    // ---- per-warp fragment geometry (M=32: halves a,b) ----
    const int m0   = warp * 32;
    const int lrow = lane & 15;
    const int lch  = lane >> 4;
    const int cb   = (lane & 3) * 2;

    const unsigned aW1 = sbase + B_W1 + (lrow * WS + lch * 8) * 2;
    const unsigned aW2 = sbase + B_W2 + (lrow * WS + lch * 8) * 2;
    const unsigned aW3 = sbase + B_W3 + (lrow * 8) * 2;

    for (int it = 0; it < TILES_PER_BLOCK; ++it) {
        const int t0 = (blockIdx.x + GX * it) * 128;
        const unsigned xoff = (it & 1) ? OFF_X1 : OFF_X0;

        cpa_wait0();
        __syncthreads();

        // prefetch next tile into the other buffer
        if (it + 1 < TILES_PER_BLOCK) {
            int tn0 = (blockIdx.x + GX * (it + 1)) * 128;
            unsigned nxoff = ((it + 1) & 1) ? OFF_X1 : OFF_X0;
            for (int c = tid; c < 640; c += 128) {
                int m = c / 5, cc = c - m * 5;
                unsigned d = sbase + nxoff + (m * XS + cc * 16) * 2;
                size_t gsrc = (size_t)(tn0 + m) * 80 + cc * 16;
                cpa16(d,     g_Xhi + gsrc);
                cpa16(d + 16, g_Xhi + gsrc + 8);
            }
            cpa_commit();
        }

        const unsigned aXa = sbase + xoff + ((m0 + lrow) * XS + lch * 8) * 2;
        const unsigned aXb = sbase + xoff + ((m0 + 16 + lrow) * XS + lch * 8) * 2;

        // ============== layer 1 (fp16 act, fp16 W; both M-halves share W frags) ==============
        float accA[16][4], accB[16][4];
#pragma unroll
        for (int j = 0; j < 16; ++j) {
            float bv0 = sb1[j * 8 + cb], bv1 = sb1[j * 8 + cb + 1];
            accA[j][0] = bv0; accA[j][1] = bv1; accA[j][2] = bv0; accA[j][3] = bv1;
            accB[j][0] = bv0; accB[j][1] = bv1; accB[j][2] = bv0; accB[j][3] = bv1;
        }
#pragma unroll
        for (int ks = 0; ks < KPAD1 / 16; ++ks) {
            unsigned aa[4], ab[4];
            ldsm4(aXa + ks * 32, aa[0], aa[1], aa[2], aa[3]);
            ldsm4(aXb + ks * 32, ab[0], ab[1], ab[2], ab[3]);
#pragma unroll
            for (int jp = 0; jp < 8; ++jp) {
                unsigned b0, b1, b2, b3;
                ldsm4t(aW1 + (ks * 16 * WS + jp * 16) * 2, b0, b1, b2, b3);
                mma_f16(accA[2 * jp],     aa, b0, b1);
                mma_f16(accA[2 * jp + 1], aa, b2, b3);
                mma_f16(accB[2 * jp],     ab, b0, b1);
                mma_f16(accB[2 * jp + 1], ab, b2, b3);
            }
        }
        // relu + pack -> layer-2 A frags (both halves)
        unsigned a2A[8][4], a2B[8][4];
#pragma unroll
        for (int kk = 0; kk < 8; ++kk) {
#pragma unroll
            for (int half = 0; half < 2; ++half) {
                int j = 2 * kk + half;
                a2A[kk][2 * half]     = packh(fmaxf(accA[j][0], 0.f), fmaxf(accA[j][1], 0.f));
                a2A[kk][2 * half + 1] = packh(fmaxf(accA[j][2], 0.f), fmaxf(accA[j][3], 0.f));
                a2B[kk][2 * half]     = packh(fmaxf(accB[j][0], 0.f), fmaxf(accB[j][1], 0.f));
                a2B[kk][2 * half + 1] = packh(fmaxf(accB[j][2], 0.f), fmaxf(accB[j][3], 0.f));
            }
        }

        // ============== layer 2 (fp16 act, fp16 W; shared W frags) ==============
        float ac2A[16][4], ac2B[16][4];
#pragma unroll
        for (int j = 0; j < 16; ++j) {
            float bv0 = sb2[j * 8 + cb], bv1 = sb2[j * 8 + cb + 1];
            ac2A[j][0] = bv0; ac2A[j][1] = bv1; ac2A[j][2] = bv0; ac2A[j][3] = bv1;
            ac2B[j][0] = bv0; ac2B[j][1] = bv1; ac2B[j][2] = bv0; ac2B[j][3] = bv1;
        }
#pragma unroll
        for (int kk = 0; kk < 8; ++kk) {
#pragma unroll
            for (int jp = 0; jp < 8; ++jp) {
                unsigned b0, b1, b2, b3;
                ldsm4t(aW2 + (kk * 16 * WS + jp * 16) * 2, b0, b1, b2, b3);
                mma_f16(ac2A[2 * jp],     a2A[kk], b0, b1);
                mma_f16(ac2A[2 * jp + 1], a2A[kk], b2, b3);
                mma_f16(ac2B[2 * jp],     a2B[kk], b0, b1);
                mma_f16(ac2B[2 * jp + 1], a2B[kk], b2, b3);
            }
        }
        // relu + pack -> layer-3 A frags
        unsigned a3A[8][4], a3B[8][4];
#pragma unroll
        for (int kk = 0; kk < 8; ++kk) {
#pragma unroll
            for (int half = 0; half < 2; ++half) {
                int j = 2 * kk + half;
                a3A[kk][2 * half]     = packh(fmaxf(ac2A[j][0], 0.f), fmaxf(ac2A[j][1], 0.f));
                a3A[kk][2 * half + 1] = packh(fmaxf(ac2A[j][2], 0.f), fmaxf(ac2A[j][3], 0.f));
                a3B[kk][2 * half]     = packh(fmaxf(ac2B[j][0], 0.f), fmaxf(ac2B[j][1], 0.f));
                a3B[kk][2 * half + 1] = packh(fmaxf(ac2B[j][2], 0.f), fmaxf(ac2B[j][3], 0.f));
            }
        }

        // ============== layer 3 (N=4 padded to 8; shared W frags) ==============
        float s3A[4][4], s3B[4][4];
        s3A[0][0] = sb3[cb]; s3A[0][1] = sb3[cb + 1];
        s3A[0][2] = s3A[0][0]; s3A[0][3] = s3A[0][1];
        s3B[0][0] = s3A[0][0]; s3B[0][1] = s3A[0][1];
        s3B[0][2] = s3A[0][0]; s3B[0][3] = s3A[0][1];
#pragma unroll
        for (int s = 1; s < 4; ++s) {
#pragma unroll
            for (int i = 0; i < 4; ++i) { s3A[s][i] = 0.f; s3B[s][i] = 0.f; }
        }
#pragma unroll
        for (int kk = 0; kk < 8; ++kk) {
            unsigned b0, b1;
            ldsm2t(aW3 + (kk * 16 * 8) * 2, b0, b1);
            mma_f16(s3A[kk & 3], a3A[kk], b0, b1);
            mma_f16(s3B[kk & 3], a3B[kk], b0, b1);
        }
        float e3A[4], e3B[4];
#pragma unroll
        for (int i = 0; i < 4; ++i) {
            e3A[i] = (s3A[0][i] + s3A[1][i]) + (s3A[2][i] + s3A[3][i]);
            e3B[i] = (s3B[0][i] + s3B[1][i]) + (s3B[2][i] + s3B[3][i]);
        }

        // store ev: cols 0-3 valid (lane%4 < 2)
        if ((lane & 3) < 2) {
            int rowA = t0 + m0 + (lane >> 2);
            long base = ((long)net * TOK + rowA) * 4 + cb;
            *(float2*)&g_ev[base] = make_float2(e3A[0], e3A[1]);
            base = ((long)net * TOK + rowA + 8) * 4 + cb;
            *(float2*)&g_ev[base] = make_float2(e3A[2], e3A[3]);
            int rowB = rowA + 16;
            base = ((long)net * TOK + rowB) * 4 + cb;
            *(float2*)&g_ev[base] = make_float2(e3B[0], e3B[1]);
            base = ((long)net * TOK + rowB + 8) * 4 + cb;
            *(float2*)&g_ev[base] = make_float2(e3B[2], e3B[3]);
        }
    }
}

// ---------------------------------------------------------------------------
// Kernel 3: combine nets with splits, volume-render per ray
// ---------------------------------------------------------------------------
__global__ void k_render(float* __restrict__ out) {
    const float* splits = out + BATCH * 3;
    __shared__ float s_scan[P_PTS];
    __shared__ float s_red[P_PTS];
    int b = blockIdx.x;
    int p = threadIdx.x;
    int t = b * P_PTS + p;

    float sp[NNET];
#pragma unroll
    for (int n = 0; n < NNET; ++n) sp[n] = splits[t * NNET + n];

    float ne0 = 0.f, ne1 = 0.f, ne2 = 0.f, ne3 = 0.f;
#pragma unroll
    for (int n = 0; n < NNET; ++n) {
        long base = ((long)n * TOK + t) * 4;
        ne0 = fmaf(g_ev[base + 0], sp[n], ne0);
        ne1 = fmaf(g_ev[base + 1], sp[n], ne1);
        ne2 = fmaf(g_ev[base + 2], sp[n], ne2);
        ne3 = fmaf(g_ev[base + 3], sp[n], ne3);
    }

    float diff = (p < 127) ? g_diffs[p] : 0.f;
    float sd = ne3 * diff;

    s_scan[p] = sd;
    __syncthreads();
#pragma unroll
    for (int off = 1; off < P_PTS; off <<= 1) {
        float v = (p >= off) ? s_scan[p - off] : 0.f;
        __syncthreads();
        s_scan[p] += v;
        __syncthreads();
    }
    float T = expf(s_scan[p]);
    float w = (p < 127) ? T * (1.0f - expf(-sd)) : 0.f;

    float col[3] = {w * ne0, w * ne1, w * ne2};
#pragma unroll
    for (int c = 0; c < 3; ++c) {
        s_red[p] = col[c];
        __syncthreads();
        for (int off = 64; off >= 1; off >>= 1) {
            if (p < off) s_red[p] += s_red[p + off];
            __syncthreads();
        }
        if (p == 0) out[b * 3 + c] = s_red[0];
        __syncthreads();
    }
}

// ---------------------------------------------------------------------------
// Launch
// ---------------------------------------------------------------------------
extern "C" void kernel_launch(void* const* d_in, const int* in_sizes, int n_in,
                              void* d_out, int out_size) {
    const float* ray_o = (const float*)d_in[0];
    const float* ray_d = (const float*)d_in[1];
    const float* s_st  = (const float*)d_in[2];
    const float* s_en  = (const float*)d_in[3];
    // d_in[4] = num_integration_points (hardcoded 128)
    const float* W1 = (const float*)d_in[5];
    const float* b1 = (const float*)d_in[6];
    const float* W2 = (const float*)d_in[7];
    const float* b2 = (const float*)d_in[8];
    const float* W3 = (const float*)d_in[9];
    const float* b3 = (const float*)d_in[10];
    const float* Ws = (const float*)d_in[11];
    const float* bs = (const float*)d_in[12];
    float* out = (float*)d_out;

    cudaFuncSetAttribute(k_mlp, cudaFuncAttributeMaxDynamicSharedMemorySize, SMEM_BYTES);

    k_init<<<1, 128>>>(s_st, s_en);
    k_prep<<<NNET, 256>>>(W1, b1, W2, b2, W3, b3);
    k_features<<<BATCH, 128>>>(ray_o, ray_d, Ws, bs, out + BATCH * 3);
    dim3 grid(GX, NNET);
    k_mlp<<<grid, 128, SMEM_BYTES>>>();
    k_render<<<BATCH, P_PTS>>>(out);
}